// round 1
// baseline (speedup 1.0000x reference)
#include <cuda_runtime.h>

#define EPSV 1e-5f

// ---------------- scratch buffers (static, allocation-free) ----------------
__device__ float g_y1[256 * 128 * 225];   // after align-conv1 + bn1 + relu   (b, c, 15*15)
__device__ float g_x2[256 * 128 * 81];    // x_  after conv7x7 + bn2 + relu   (b, c, 9*9)
__device__ float g_y3[256 * 128 * 81];    // after conv3 + bn3 + relu
__device__ float g_merge[256 * 128 * 81]; // after conv4 + bn4 + relu
__device__ float g_logits[256 * 81];      // attention logits

// ============================================================================
// Kernel 1: align + conv1x1 (841 -> 128) + bn1 + relu
// For spatial (i,j) only channels k = a*15+bb are valid, weight index
// w1[o, (a+14-i)*29 + (bb+14-j)].  GEMM per spatial pos: M=256(batch) K=225 N=128.
// grid (225, 4), block 256
// ============================================================================
__global__ __launch_bounds__(256) void k1_alignconv(
    const float* __restrict__ x, const float* __restrict__ w1,
    const float* __restrict__ b1, const float* __restrict__ bn1)
{
    __shared__ __align__(16) float As[32][68];
    __shared__ __align__(16) float Bs[32][132];
    const int tid = threadIdx.x;
    const int ij  = blockIdx.x;
    const int ip  = ij / 15, jp = ij - ip * 15;
    const int m0  = blockIdx.y * 64;

    const int m_l = tid & 63;        // A: m row (batch)
    const int klb = tid >> 6;        // A: k base 0..3
    const int bkl = tid & 31;        // B: k
    const int bnb = tid >> 5;        // B: n base 0..7
    const int tm4 = (tid >> 4) << 2; // compute: 4 m rows
    const int tn8 = (tid & 15) << 3; // compute: 8 n cols

    const float* xp = x + (long)(m0 + m_l) * 50625 + ij;

    float acc[4][8];
#pragma unroll
    for (int i = 0; i < 4; i++)
#pragma unroll
        for (int j = 0; j < 8; j++) acc[i][j] = 0.f;

    for (int k0 = 0; k0 < 225; k0 += 32) {
#pragma unroll
        for (int i = 0; i < 8; i++) {
            int kl = klb + i * 4;
            int k  = k0 + kl;
            As[kl][m_l] = (k < 225) ? xp[k * 225] : 0.f;
        }
#pragma unroll
        for (int i = 0; i < 16; i++) {
            int n = bnb + i * 8;
            int k = k0 + bkl;
            float v = 0.f;
            if (k < 225) {
                int a = k / 15, bb = k - a * 15;
                v = w1[n * 841 + (a + 14 - ip) * 29 + (bb + 14 - jp)];
            }
            Bs[bkl][n] = v;
        }
        __syncthreads();
#pragma unroll
        for (int kk = 0; kk < 32; kk++) {
            float4 av  = *(const float4*)&As[kk][tm4];
            float4 bv0 = *(const float4*)&Bs[kk][tn8];
            float4 bv1 = *(const float4*)&Bs[kk][tn8 + 4];
            float a4[4] = {av.x, av.y, av.z, av.w};
            float b8[8] = {bv0.x, bv0.y, bv0.z, bv0.w, bv1.x, bv1.y, bv1.z, bv1.w};
#pragma unroll
            for (int i = 0; i < 4; i++)
#pragma unroll
                for (int j = 0; j < 8; j++) acc[i][j] = fmaf(a4[i], b8[j], acc[i][j]);
        }
        __syncthreads();
    }

    float sc[8], sh[8];
#pragma unroll
    for (int j = 0; j < 8; j++) {
        int n = tn8 + j;
        float g = bn1[n], be = bn1[128 + n], mu = bn1[256 + n], va = bn1[384 + n];
        float s = g * rsqrtf(va + EPSV);
        sc[j] = s;
        sh[j] = (b1[n] - mu) * s + be;
    }
#pragma unroll
    for (int i = 0; i < 4; i++) {
        int m = m0 + tm4 + i;
        float* yp = g_y1 + (long)m * 28800 + ij;
#pragma unroll
        for (int j = 0; j < 8; j++) {
            yp[(tn8 + j) * 225] = fmaxf(fmaf(acc[i][j], sc[j], sh[j]), 0.f);
        }
    }
}

// ============================================================================
// Kernel 2: 7x7 conv 128->128, 15x15 -> 9x9, + bn2 + relu  (implicit GEMM)
// M = 256*81 = 20736, N = 128, K = 128*49 = 6272.  grid 324, block 256
// ============================================================================
__global__ __launch_bounds__(256) void k2_conv7(
    const float* __restrict__ w2, const float* __restrict__ b2,
    const float* __restrict__ bn2)
{
    __shared__ __align__(16) float As[32][68];
    __shared__ __align__(16) float Bs[32][132];
    const int tid = threadIdx.x;
    const int m0  = blockIdx.x * 64;
    const int m_l = tid & 63;
    const int klb = tid >> 6;
    const int bkl = tid & 31;
    const int bnb = tid >> 5;
    const int tm4 = (tid >> 4) << 2;
    const int tn8 = (tid & 15) << 3;

    const int m  = m0 + m_l;
    const int b  = m / 81;
    const int pos = m - b * 81;
    const int oh = pos / 9;
    const int ow = pos - oh * 9;
    const float* ap = g_y1 + (long)b * 28800 + oh * 15 + ow;

    float acc[4][8];
#pragma unroll
    for (int i = 0; i < 4; i++)
#pragma unroll
        for (int j = 0; j < 8; j++) acc[i][j] = 0.f;

    for (int k0 = 0; k0 < 6272; k0 += 32) {
#pragma unroll
        for (int i = 0; i < 8; i++) {
            int kl = klb + i * 4;
            int k  = k0 + kl;
            int ci = k / 49;
            int r  = k - ci * 49;
            int kh = r / 7;
            int kw = r - kh * 7;
            As[kl][m_l] = ap[ci * 225 + kh * 15 + kw];
        }
#pragma unroll
        for (int i = 0; i < 16; i++) {
            int n = bnb + i * 8;
            Bs[bkl][n] = w2[n * 6272 + k0 + bkl];
        }
        __syncthreads();
#pragma unroll
        for (int kk = 0; kk < 32; kk++) {
            float4 av  = *(const float4*)&As[kk][tm4];
            float4 bv0 = *(const float4*)&Bs[kk][tn8];
            float4 bv1 = *(const float4*)&Bs[kk][tn8 + 4];
            float a4[4] = {av.x, av.y, av.z, av.w};
            float b8[8] = {bv0.x, bv0.y, bv0.z, bv0.w, bv1.x, bv1.y, bv1.z, bv1.w};
#pragma unroll
            for (int i = 0; i < 4; i++)
#pragma unroll
                for (int j = 0; j < 8; j++) acc[i][j] = fmaf(a4[i], b8[j], acc[i][j]);
        }
        __syncthreads();
    }

    float sc[8], sh[8];
#pragma unroll
    for (int j = 0; j < 8; j++) {
        int n = tn8 + j;
        float g = bn2[n], be = bn2[128 + n], mu = bn2[256 + n], va = bn2[384 + n];
        float s = g * rsqrtf(va + EPSV);
        sc[j] = s;
        sh[j] = (b2[n] - mu) * s + be;
    }
#pragma unroll
    for (int i = 0; i < 4; i++) {
        int mi = m0 + tm4 + i;
        int bb = mi / 81;
        int pp = mi - bb * 81;
#pragma unroll
        for (int j = 0; j < 8; j++) {
            int n = tn8 + j;
            g_x2[((long)bb * 128 + n) * 81 + pp] = fmaxf(fmaf(acc[i][j], sc[j], sh[j]), 0.f);
        }
    }
}

// ============================================================================
// Kernel 3: concat(weight(5), x_(128)) -> conv1x1 133->128 + bn3 + relu
// M=20736, N=128, K=133 (pad to 160). grid 324, block 256
// ============================================================================
__global__ __launch_bounds__(256) void k3_conv3(
    const float* __restrict__ wgt, const float* __restrict__ w3,
    const float* __restrict__ b3, const float* __restrict__ bn3)
{
    __shared__ __align__(16) float As[32][68];
    __shared__ __align__(16) float Bs[32][132];
    const int tid = threadIdx.x;
    const int m0  = blockIdx.x * 64;
    const int m_l = tid & 63;
    const int klb = tid >> 6;
    const int bkl = tid & 31;
    const int bnb = tid >> 5;
    const int tm4 = (tid >> 4) << 2;
    const int tn8 = (tid & 15) << 3;

    const int m   = m0 + m_l;
    const int b   = m / 81;
    const int pos = m - b * 81;

    float acc[4][8];
#pragma unroll
    for (int i = 0; i < 4; i++)
#pragma unroll
        for (int j = 0; j < 8; j++) acc[i][j] = 0.f;

    for (int k0 = 0; k0 < 160; k0 += 32) {
#pragma unroll
        for (int i = 0; i < 8; i++) {
            int kl = klb + i * 4;
            int k  = k0 + kl;
            float v = 0.f;
            if (k < 5)        v = wgt[k * 81 + pos];
            else if (k < 133) v = g_x2[((long)b * 128 + (k - 5)) * 81 + pos];
            As[kl][m_l] = v;
        }
#pragma unroll
        for (int i = 0; i < 16; i++) {
            int n = bnb + i * 8;
            int k = k0 + bkl;
            Bs[bkl][n] = (k < 133) ? w3[n * 133 + k] : 0.f;
        }
        __syncthreads();
#pragma unroll
        for (int kk = 0; kk < 32; kk++) {
            float4 av  = *(const float4*)&As[kk][tm4];
            float4 bv0 = *(const float4*)&Bs[kk][tn8];
            float4 bv1 = *(const float4*)&Bs[kk][tn8 + 4];
            float a4[4] = {av.x, av.y, av.z, av.w};
            float b8[8] = {bv0.x, bv0.y, bv0.z, bv0.w, bv1.x, bv1.y, bv1.z, bv1.w};
#pragma unroll
            for (int i = 0; i < 4; i++)
#pragma unroll
                for (int j = 0; j < 8; j++) acc[i][j] = fmaf(a4[i], b8[j], acc[i][j]);
        }
        __syncthreads();
    }

    float sc[8], sh[8];
#pragma unroll
    for (int j = 0; j < 8; j++) {
        int n = tn8 + j;
        float g = bn3[n], be = bn3[128 + n], mu = bn3[256 + n], va = bn3[384 + n];
        float s = g * rsqrtf(va + EPSV);
        sc[j] = s;
        sh[j] = (b3[n] - mu) * s + be;
    }
#pragma unroll
    for (int i = 0; i < 4; i++) {
        int mi = m0 + tm4 + i;
        int bb = mi / 81;
        int pp = mi - bb * 81;
#pragma unroll
        for (int j = 0; j < 8; j++) {
            int n = tn8 + j;
            g_y3[((long)bb * 128 + n) * 81 + pp] = fmaxf(fmaf(acc[i][j], sc[j], sh[j]), 0.f);
        }
    }
}

// ============================================================================
// Kernel 4: conv1x1 128->128 + bn4 + relu -> merge.  M=20736 K=128 N=128
// ============================================================================
__global__ __launch_bounds__(256) void k4_conv4(
    const float* __restrict__ w4, const float* __restrict__ b4,
    const float* __restrict__ bn4)
{
    __shared__ __align__(16) float As[32][68];
    __shared__ __align__(16) float Bs[32][132];
    const int tid = threadIdx.x;
    const int m0  = blockIdx.x * 64;
    const int m_l = tid & 63;
    const int klb = tid >> 6;
    const int bkl = tid & 31;
    const int bnb = tid >> 5;
    const int tm4 = (tid >> 4) << 2;
    const int tn8 = (tid & 15) << 3;

    const int m   = m0 + m_l;
    const int b   = m / 81;
    const int pos = m - b * 81;

    float acc[4][8];
#pragma unroll
    for (int i = 0; i < 4; i++)
#pragma unroll
        for (int j = 0; j < 8; j++) acc[i][j] = 0.f;

    for (int k0 = 0; k0 < 128; k0 += 32) {
#pragma unroll
        for (int i = 0; i < 8; i++) {
            int kl = klb + i * 4;
            int k  = k0 + kl;
            As[kl][m_l] = g_y3[((long)b * 128 + k) * 81 + pos];
        }
#pragma unroll
        for (int i = 0; i < 16; i++) {
            int n = bnb + i * 8;
            Bs[bkl][n] = w4[n * 128 + k0 + bkl];
        }
        __syncthreads();
#pragma unroll
        for (int kk = 0; kk < 32; kk++) {
            float4 av  = *(const float4*)&As[kk][tm4];
            float4 bv0 = *(const float4*)&Bs[kk][tn8];
            float4 bv1 = *(const float4*)&Bs[kk][tn8 + 4];
            float a4[4] = {av.x, av.y, av.z, av.w};
            float b8[8] = {bv0.x, bv0.y, bv0.z, bv0.w, bv1.x, bv1.y, bv1.z, bv1.w};
#pragma unroll
            for (int i = 0; i < 4; i++)
#pragma unroll
                for (int j = 0; j < 8; j++) acc[i][j] = fmaf(a4[i], b8[j], acc[i][j]);
        }
        __syncthreads();
    }

    float sc[8], sh[8];
#pragma unroll
    for (int j = 0; j < 8; j++) {
        int n = tn8 + j;
        float g = bn4[n], be = bn4[128 + n], mu = bn4[256 + n], va = bn4[384 + n];
        float s = g * rsqrtf(va + EPSV);
        sc[j] = s;
        sh[j] = (b4[n] - mu) * s + be;
    }
#pragma unroll
    for (int i = 0; i < 4; i++) {
        int mi = m0 + tm4 + i;
        int bb = mi / 81;
        int pp = mi - bb * 81;
#pragma unroll
        for (int j = 0; j < 8; j++) {
            int n = tn8 + j;
            g_merge[((long)bb * 128 + n) * 81 + pp] = fmaxf(fmaf(acc[i][j], sc[j], sh[j]), 0.f);
        }
    }
}

// ============================================================================
// Kernel 5: attention logits.  per (b,pos): t = relu(bna(wa1 @ x_ + ba1));
// logit = wa2 . t + ba2.   grid 256*81, block 64
// ============================================================================
__global__ __launch_bounds__(64) void k5_logits(
    const float* __restrict__ wa1, const float* __restrict__ ba1,
    const float* __restrict__ bna, const float* __restrict__ wa2,
    const float* __restrict__ ba2)
{
    __shared__ float xs[128];
    __shared__ float red[2];
    const int bp  = blockIdx.x;
    const int b   = bp / 81;
    const int pos = bp - b * 81;
    const int o   = threadIdx.x;  // 0..63

    xs[o]      = g_x2[((long)b * 128 + o) * 81 + pos];
    xs[o + 64] = g_x2[((long)b * 128 + o + 64) * 81 + pos];
    __syncthreads();

    float acc = 0.f;
    const float* wr = wa1 + o * 128;
#pragma unroll 8
    for (int c = 0; c < 128; c++) acc = fmaf(wr[c], xs[c], acc);

    float g = bna[o], be = bna[64 + o], mu = bna[128 + o], va = bna[192 + o];
    float s = g * rsqrtf(va + EPSV);
    float t = fmaxf((acc + ba1[o] - mu) * s + be, 0.f);
    float p = wa2[o] * t;
#pragma unroll
    for (int off = 16; off > 0; off >>= 1) p += __shfl_down_sync(0xffffffffu, p, off);
    if ((o & 31) == 0) red[o >> 5] = p;
    __syncthreads();
    if (o == 0) g_logits[bp] = red[0] + red[1] + ba2[0];
}

// ============================================================================
// Kernel 6: softmax(81) + attention-pool + final linear (128->6)
// grid 256, block 128
// ============================================================================
__global__ __launch_bounds__(128) void k6_final(
    const float* __restrict__ wl, const float* __restrict__ bl,
    float* __restrict__ out)
{
    __shared__ float att[81];
    __shared__ float pooled[128];
    __shared__ float red[4];
    const int b = blockIdx.x;
    const int t = threadIdx.x;

    float v = (t < 81) ? g_logits[b * 81 + t] : -1e30f;
    float mx = v;
#pragma unroll
    for (int off = 16; off > 0; off >>= 1) mx = fmaxf(mx, __shfl_xor_sync(0xffffffffu, mx, off));
    if ((t & 31) == 0) red[t >> 5] = mx;
    __syncthreads();
    mx = fmaxf(fmaxf(red[0], red[1]), fmaxf(red[2], red[3]));
    float e = (t < 81) ? expf(v - mx) : 0.f;
    __syncthreads();  // all threads done reading red
    float sm = e;
#pragma unroll
    for (int off = 16; off > 0; off >>= 1) sm += __shfl_xor_sync(0xffffffffu, sm, off);
    if ((t & 31) == 0) red[t >> 5] = sm;
    __syncthreads();
    sm = red[0] + red[1] + red[2] + red[3];
    if (t < 81) att[t] = e / sm;
    __syncthreads();

    float acc = 0.f;
    const float* mr = g_merge + ((long)b * 128 + t) * 81;
#pragma unroll 9
    for (int p = 0; p < 81; p++) acc = fmaf(att[p], mr[p], acc);
    pooled[t] = acc;
    __syncthreads();

    if (t < 6) {
        float s2 = bl[t];
        const float* wr = wl + t * 128;
#pragma unroll 8
        for (int o = 0; o < 128; o++) s2 = fmaf(wr[o], pooled[o], s2);
        out[b * 6 + t] = s2;
    }
}

// ============================================================================
extern "C" void kernel_launch(void* const* d_in, const int* in_sizes, int n_in,
                              void* d_out, int out_size)
{
    const float* x    = (const float*)d_in[0];
    const float* w1   = (const float*)d_in[1];
    const float* b1   = (const float*)d_in[2];
    const float* bn1  = (const float*)d_in[3];
    const float* w2   = (const float*)d_in[4];
    const float* b2   = (const float*)d_in[5];
    const float* bn2  = (const float*)d_in[6];
    const float* wgt  = (const float*)d_in[7];
    const float* w3   = (const float*)d_in[8];
    const float* b3   = (const float*)d_in[9];
    const float* bn3  = (const float*)d_in[10];
    const float* w4   = (const float*)d_in[11];
    const float* b4   = (const float*)d_in[12];
    const float* bn4  = (const float*)d_in[13];
    const float* wa1  = (const float*)d_in[14];
    const float* ba1  = (const float*)d_in[15];
    const float* bna  = (const float*)d_in[16];
    const float* wa2  = (const float*)d_in[17];
    const float* ba2  = (const float*)d_in[18];
    const float* wl   = (const float*)d_in[19];
    const float* bl   = (const float*)d_in[20];
    float* out = (float*)d_out;

    dim3 g1(225, 4);
    k1_alignconv<<<g1, 256>>>(x, w1, b1, bn1);
    k2_conv7<<<324, 256>>>(w2, b2, bn2);
    k3_conv3<<<324, 256>>>(wgt, w3, b3, bn3);
    k4_conv4<<<324, 256>>>(w4, b4, bn4);
    k5_logits<<<256 * 81, 64>>>(wa1, ba1, bna, wa2, ba2);
    k6_final<<<256, 128>>>(wl, bl, out);
}

// round 2
// speedup vs baseline: 1.3344x; 1.3344x over previous
#include <cuda_runtime.h>

#define EPSV 1e-5f

typedef unsigned long long ull;

// ---------------- scratch buffers (static, allocation-free) ----------------
__device__ float g_y1[256 * 128 * 225];   // after align-conv1 + bn1 + relu   (b, c, 15*15)
__device__ float g_x2[256 * 128 * 81];    // x_  after conv7x7 + bn2 + relu   (b, c, 9*9)
__device__ float g_y3[256 * 128 * 81];    // after conv3 + bn3 + relu
__device__ float g_merge[256 * 128 * 81]; // after conv4 + bn4 + relu
__device__ float g_logits[256 * 81];      // attention logits
__device__ float g_p[4 * 20736 * 128];    // K-split partial sums for conv7x7

// packed fp32x2 FMA helpers (sm_100+)
__device__ __forceinline__ void ffma2(ull& d, ull a, ull b) {
    asm("fma.rn.f32x2 %0, %1, %2, %0;" : "+l"(d) : "l"(a), "l"(b));
}
__device__ __forceinline__ ull pack2(float x) {
    ull r;
    asm("mov.b64 %0, {%1, %1};" : "=l"(r) : "f"(x));
    return r;
}

// ============================================================================
// Kernel 1: align + conv1x1 (841 -> 128) + bn1 + relu
// ============================================================================
__global__ __launch_bounds__(256) void k1_alignconv(
    const float* __restrict__ x, const float* __restrict__ w1,
    const float* __restrict__ b1, const float* __restrict__ bn1)
{
    __shared__ __align__(16) float As[32][68];
    __shared__ __align__(16) float Bs[32][132];
    const int tid = threadIdx.x;
    const int ij  = blockIdx.x;
    const int ip  = ij / 15, jp = ij - ip * 15;
    const int m0  = blockIdx.y * 64;

    const int m_l = tid & 63;
    const int klb = tid >> 6;
    const int bkl = tid & 31;
    const int bnb = tid >> 5;
    const int tm4 = (tid >> 4) << 2;
    const int tn8 = (tid & 15) << 3;

    const float* xp = x + (long)(m0 + m_l) * 50625 + ij;

    float acc[4][8];
#pragma unroll
    for (int i = 0; i < 4; i++)
#pragma unroll
        for (int j = 0; j < 8; j++) acc[i][j] = 0.f;

    for (int k0 = 0; k0 < 225; k0 += 32) {
#pragma unroll
        for (int i = 0; i < 8; i++) {
            int kl = klb + i * 4;
            int k  = k0 + kl;
            As[kl][m_l] = (k < 225) ? xp[k * 225] : 0.f;
        }
#pragma unroll
        for (int i = 0; i < 16; i++) {
            int n = bnb + i * 8;
            int k = k0 + bkl;
            float v = 0.f;
            if (k < 225) {
                int a = k / 15, bb = k - a * 15;
                v = w1[n * 841 + (a + 14 - ip) * 29 + (bb + 14 - jp)];
            }
            Bs[bkl][n] = v;
        }
        __syncthreads();
#pragma unroll
        for (int kk = 0; kk < 32; kk++) {
            float4 av  = *(const float4*)&As[kk][tm4];
            float4 bv0 = *(const float4*)&Bs[kk][tn8];
            float4 bv1 = *(const float4*)&Bs[kk][tn8 + 4];
            float a4[4] = {av.x, av.y, av.z, av.w};
            float b8[8] = {bv0.x, bv0.y, bv0.z, bv0.w, bv1.x, bv1.y, bv1.z, bv1.w};
#pragma unroll
            for (int i = 0; i < 4; i++)
#pragma unroll
                for (int j = 0; j < 8; j++) acc[i][j] = fmaf(a4[i], b8[j], acc[i][j]);
        }
        __syncthreads();
    }

    float sc[8], sh[8];
#pragma unroll
    for (int j = 0; j < 8; j++) {
        int n = tn8 + j;
        float g = bn1[n], be = bn1[128 + n], mu = bn1[256 + n], va = bn1[384 + n];
        float s = g * rsqrtf(va + EPSV);
        sc[j] = s;
        sh[j] = (b1[n] - mu) * s + be;
    }
#pragma unroll
    for (int i = 0; i < 4; i++) {
        int m = m0 + tm4 + i;
        float* yp = g_y1 + (long)m * 28800 + ij;
#pragma unroll
        for (int j = 0; j < 8; j++) {
            yp[(tn8 + j) * 225] = fmaxf(fmaf(acc[i][j], sc[j], sh[j]), 0.f);
        }
    }
}

// ============================================================================
// Kernel 2 (NEW): 7x7 conv implicit GEMM, M=20736 N=128 K=6272.
// 128x128 block tile, 256 threads, 8x8 per thread via fma.rn.f32x2,
// double-buffered smem, K-split x4 across blockIdx.y -> g_p partials.
// grid (162, 4), block 256
// ============================================================================
__global__ __launch_bounds__(256) void k2_gemm(const float* __restrict__ w2)
{
    __shared__ __align__(16) float As[2][16][132];
    __shared__ __align__(16) float Bs[2][16][132];
    const int tid  = threadIdx.x;
    const int m0   = blockIdx.x * 128;
    const int kbeg = blockIdx.y * 1568;
    float* outp = g_p + (long)blockIdx.y * (20736 * 128);

    // loader mapping
    const int lm = tid & 127;       // A: local m / B: n
    const int lk = (tid >> 7) * 8;  // k sub-offset: 0 or 8
    const int gm = m0 + lm;
    const int bb_ = gm / 81;
    const int pos_ = gm - bb_ * 81;
    const int oh = pos_ / 9, ow = pos_ - oh * 9;
    const float* abase = g_y1 + (long)bb_ * 28800 + oh * 15 + ow;
    const float* bbase = w2 + (long)lm * 6272 + kbeg + lk;

    // compute mapping
    const int tx = tid & 15;   // n block: tx*8
    const int ty = tid >> 4;   // m block: ty*8

    ull acc[8][4];
#pragma unroll
    for (int i = 0; i < 8; i++)
#pragma unroll
        for (int j = 0; j < 4; j++) acc[i][j] = 0ull;

    float ra[8];
    float4 rb0, rb1;

    // ---- prologue: load ktile 0 ----
    {
        int k0 = kbeg + lk;
#pragma unroll
        for (int j = 0; j < 8; j++) {
            int k  = k0 + j;
            int ci = k / 49;
            int r  = k - ci * 49;
            int kh = r / 7;
            int kw = r - kh * 7;
            ra[j] = __ldg(abase + ci * 225 + kh * 15 + kw);
        }
        const float4* bp4 = (const float4*)bbase;
        rb0 = bp4[0];
        rb1 = bp4[1];
    }
    // store tile 0 -> buf 0
#pragma unroll
    for (int j = 0; j < 8; j++) As[0][lk + j][lm] = ra[j];
    Bs[0][lk + 0][lm] = rb0.x; Bs[0][lk + 1][lm] = rb0.y;
    Bs[0][lk + 2][lm] = rb0.z; Bs[0][lk + 3][lm] = rb0.w;
    Bs[0][lk + 4][lm] = rb1.x; Bs[0][lk + 5][lm] = rb1.y;
    Bs[0][lk + 6][lm] = rb1.z; Bs[0][lk + 7][lm] = rb1.w;
    __syncthreads();

    int buf = 0;
    for (int kt = 1; kt < 98; kt++) {
        // prefetch next ktile
        {
            int k0 = kbeg + kt * 16 + lk;
#pragma unroll
            for (int j = 0; j < 8; j++) {
                int k  = k0 + j;
                int ci = k / 49;
                int r  = k - ci * 49;
                int kh = r / 7;
                int kw = r - kh * 7;
                ra[j] = __ldg(abase + ci * 225 + kh * 15 + kw);
            }
            const float4* bp4 = (const float4*)(bbase + kt * 16);
            rb0 = bp4[0];
            rb1 = bp4[1];
        }
        // compute current buffer
#pragma unroll
        for (int kk = 0; kk < 16; kk++) {
            float4 a0 = *(const float4*)&As[buf][kk][ty * 8];
            float4 a1 = *(const float4*)&As[buf][kk][ty * 8 + 4];
            ulonglong2 b0 = *(const ulonglong2*)&Bs[buf][kk][tx * 8];
            ulonglong2 b1 = *(const ulonglong2*)&Bs[buf][kk][tx * 8 + 4];
            ull bp_[4] = {b0.x, b0.y, b1.x, b1.y};
            float af[8] = {a0.x, a0.y, a0.z, a0.w, a1.x, a1.y, a1.z, a1.w};
#pragma unroll
            for (int i = 0; i < 8; i++) {
                ull pa = pack2(af[i]);
#pragma unroll
                for (int j = 0; j < 4; j++) ffma2(acc[i][j], pa, bp_[j]);
            }
        }
        // store prefetched tile into other buffer
        int nb = buf ^ 1;
#pragma unroll
        for (int j = 0; j < 8; j++) As[nb][lk + j][lm] = ra[j];
        Bs[nb][lk + 0][lm] = rb0.x; Bs[nb][lk + 1][lm] = rb0.y;
        Bs[nb][lk + 2][lm] = rb0.z; Bs[nb][lk + 3][lm] = rb0.w;
        Bs[nb][lk + 4][lm] = rb1.x; Bs[nb][lk + 5][lm] = rb1.y;
        Bs[nb][lk + 6][lm] = rb1.z; Bs[nb][lk + 7][lm] = rb1.w;
        __syncthreads();
        buf = nb;
    }
    // final tile
#pragma unroll
    for (int kk = 0; kk < 16; kk++) {
        float4 a0 = *(const float4*)&As[buf][kk][ty * 8];
        float4 a1 = *(const float4*)&As[buf][kk][ty * 8 + 4];
        ulonglong2 b0 = *(const ulonglong2*)&Bs[buf][kk][tx * 8];
        ulonglong2 b1 = *(const ulonglong2*)&Bs[buf][kk][tx * 8 + 4];
        ull bp_[4] = {b0.x, b0.y, b1.x, b1.y};
        float af[8] = {a0.x, a0.y, a0.z, a0.w, a1.x, a1.y, a1.z, a1.w};
#pragma unroll
        for (int i = 0; i < 8; i++) {
            ull pa = pack2(af[i]);
#pragma unroll
            for (int j = 0; j < 4; j++) ffma2(acc[i][j], pa, bp_[j]);
        }
    }

    // write partials (raw sums, no bn/relu yet)
#pragma unroll
    for (int i = 0; i < 8; i++) {
        int m = m0 + ty * 8 + i;
        ull* op = (ull*)(outp + (long)m * 128 + tx * 8);
#pragma unroll
        for (int j = 0; j < 4; j++) op[j] = acc[i][j];
    }
}

// ============================================================================
// Kernel 2e: sum 4 K-split partials + bias + bn2 + relu -> g_x2 ([b][c][81])
// grid 2592, block 256 (each thread: one m, 4 n channels)
// ============================================================================
__global__ __launch_bounds__(256) void k2e(
    const float* __restrict__ b2, const float* __restrict__ bn2)
{
    const long CH = 20736L * 128L;
    int t  = blockIdx.x * 256 + threadIdx.x;   // [0, 20736*32)
    int m  = t >> 5;
    int n4 = (t & 31) << 2;
    long idx = (long)m * 128 + n4;

    float4 p0 = *(const float4*)(g_p + idx);
    float4 p1 = *(const float4*)(g_p + CH + idx);
    float4 p2 = *(const float4*)(g_p + 2 * CH + idx);
    float4 p3 = *(const float4*)(g_p + 3 * CH + idx);
    float s[4] = {p0.x + p1.x + p2.x + p3.x,
                  p0.y + p1.y + p2.y + p3.y,
                  p0.z + p1.z + p2.z + p3.z,
                  p0.w + p1.w + p2.w + p3.w};

    int b   = m / 81;
    int pos = m - b * 81;
#pragma unroll
    for (int j = 0; j < 4; j++) {
        int n = n4 + j;
        float g = bn2[n], be = bn2[128 + n], mu = bn2[256 + n], va = bn2[384 + n];
        float sc = g * rsqrtf(va + EPSV);
        float v  = fmaxf((s[j] + b2[n] - mu) * sc + be, 0.f);
        g_x2[((long)b * 128 + n) * 81 + pos] = v;
    }
}

// ============================================================================
// Kernel 3: concat(weight(5), x_(128)) -> conv1x1 133->128 + bn3 + relu
// ============================================================================
__global__ __launch_bounds__(256) void k3_conv3(
    const float* __restrict__ wgt, const float* __restrict__ w3,
    const float* __restrict__ b3, const float* __restrict__ bn3)
{
    __shared__ __align__(16) float As[32][68];
    __shared__ __align__(16) float Bs[32][132];
    const int tid = threadIdx.x;
    const int m0  = blockIdx.x * 64;
    const int m_l = tid & 63;
    const int klb = tid >> 6;
    const int bkl = tid & 31;
    const int bnb = tid >> 5;
    const int tm4 = (tid >> 4) << 2;
    const int tn8 = (tid & 15) << 3;

    const int m   = m0 + m_l;
    const int b   = m / 81;
    const int pos = m - b * 81;

    float acc[4][8];
#pragma unroll
    for (int i = 0; i < 4; i++)
#pragma unroll
        for (int j = 0; j < 8; j++) acc[i][j] = 0.f;

    for (int k0 = 0; k0 < 160; k0 += 32) {
#pragma unroll
        for (int i = 0; i < 8; i++) {
            int kl = klb + i * 4;
            int k  = k0 + kl;
            float v = 0.f;
            if (k < 5)        v = wgt[k * 81 + pos];
            else if (k < 133) v = g_x2[((long)b * 128 + (k - 5)) * 81 + pos];
            As[kl][m_l] = v;
        }
#pragma unroll
        for (int i = 0; i < 16; i++) {
            int n = bnb + i * 8;
            int k = k0 + bkl;
            Bs[bkl][n] = (k < 133) ? w3[n * 133 + k] : 0.f;
        }
        __syncthreads();
#pragma unroll
        for (int kk = 0; kk < 32; kk++) {
            float4 av  = *(const float4*)&As[kk][tm4];
            float4 bv0 = *(const float4*)&Bs[kk][tn8];
            float4 bv1 = *(const float4*)&Bs[kk][tn8 + 4];
            float a4[4] = {av.x, av.y, av.z, av.w};
            float b8[8] = {bv0.x, bv0.y, bv0.z, bv0.w, bv1.x, bv1.y, bv1.z, bv1.w};
#pragma unroll
            for (int i = 0; i < 4; i++)
#pragma unroll
                for (int j = 0; j < 8; j++) acc[i][j] = fmaf(a4[i], b8[j], acc[i][j]);
        }
        __syncthreads();
    }

    float sc[8], sh[8];
#pragma unroll
    for (int j = 0; j < 8; j++) {
        int n = tn8 + j;
        float g = bn3[n], be = bn3[128 + n], mu = bn3[256 + n], va = bn3[384 + n];
        float s = g * rsqrtf(va + EPSV);
        sc[j] = s;
        sh[j] = (b3[n] - mu) * s + be;
    }
#pragma unroll
    for (int i = 0; i < 4; i++) {
        int mi = m0 + tm4 + i;
        int bbv = mi / 81;
        int pp = mi - bbv * 81;
#pragma unroll
        for (int j = 0; j < 8; j++) {
            int n = tn8 + j;
            g_y3[((long)bbv * 128 + n) * 81 + pp] = fmaxf(fmaf(acc[i][j], sc[j], sh[j]), 0.f);
        }
    }
}

// ============================================================================
// Kernel 4: conv1x1 128->128 + bn4 + relu -> merge
// ============================================================================
__global__ __launch_bounds__(256) void k4_conv4(
    const float* __restrict__ w4, const float* __restrict__ b4,
    const float* __restrict__ bn4)
{
    __shared__ __align__(16) float As[32][68];
    __shared__ __align__(16) float Bs[32][132];
    const int tid = threadIdx.x;
    const int m0  = blockIdx.x * 64;
    const int m_l = tid & 63;
    const int klb = tid >> 6;
    const int bkl = tid & 31;
    const int bnb = tid >> 5;
    const int tm4 = (tid >> 4) << 2;
    const int tn8 = (tid & 15) << 3;

    const int m   = m0 + m_l;
    const int b   = m / 81;
    const int pos = m - b * 81;

    float acc[4][8];
#pragma unroll
    for (int i = 0; i < 4; i++)
#pragma unroll
        for (int j = 0; j < 8; j++) acc[i][j] = 0.f;

    for (int k0 = 0; k0 < 128; k0 += 32) {
#pragma unroll
        for (int i = 0; i < 8; i++) {
            int kl = klb + i * 4;
            int k  = k0 + kl;
            As[kl][m_l] = g_y3[((long)b * 128 + k) * 81 + pos];
        }
#pragma unroll
        for (int i = 0; i < 16; i++) {
            int n = bnb + i * 8;
            Bs[bkl][n] = w4[n * 128 + k0 + bkl];
        }
        __syncthreads();
#pragma unroll
        for (int kk = 0; kk < 32; kk++) {
            float4 av  = *(const float4*)&As[kk][tm4];
            float4 bv0 = *(const float4*)&Bs[kk][tn8];
            float4 bv1 = *(const float4*)&Bs[kk][tn8 + 4];
            float a4[4] = {av.x, av.y, av.z, av.w};
            float b8[8] = {bv0.x, bv0.y, bv0.z, bv0.w, bv1.x, bv1.y, bv1.z, bv1.w};
#pragma unroll
            for (int i = 0; i < 4; i++)
#pragma unroll
                for (int j = 0; j < 8; j++) acc[i][j] = fmaf(a4[i], b8[j], acc[i][j]);
        }
        __syncthreads();
    }

    float sc[8], sh[8];
#pragma unroll
    for (int j = 0; j < 8; j++) {
        int n = tn8 + j;
        float g = bn4[n], be = bn4[128 + n], mu = bn4[256 + n], va = bn4[384 + n];
        float s = g * rsqrtf(va + EPSV);
        sc[j] = s;
        sh[j] = (b4[n] - mu) * s + be;
    }
#pragma unroll
    for (int i = 0; i < 4; i++) {
        int mi = m0 + tm4 + i;
        int bbv = mi / 81;
        int pp = mi - bbv * 81;
#pragma unroll
        for (int j = 0; j < 8; j++) {
            int n = tn8 + j;
            g_merge[((long)bbv * 128 + n) * 81 + pp] = fmaxf(fmaf(acc[i][j], sc[j], sh[j]), 0.f);
        }
    }
}

// ============================================================================
// Kernel 5: attention logits
// ============================================================================
__global__ __launch_bounds__(64) void k5_logits(
    const float* __restrict__ wa1, const float* __restrict__ ba1,
    const float* __restrict__ bna, const float* __restrict__ wa2,
    const float* __restrict__ ba2)
{
    __shared__ float xs[128];
    __shared__ float red[2];
    const int bp  = blockIdx.x;
    const int b   = bp / 81;
    const int pos = bp - b * 81;
    const int o   = threadIdx.x;  // 0..63

    xs[o]      = g_x2[((long)b * 128 + o) * 81 + pos];
    xs[o + 64] = g_x2[((long)b * 128 + o + 64) * 81 + pos];
    __syncthreads();

    float acc = 0.f;
    const float* wr = wa1 + o * 128;
#pragma unroll 8
    for (int c = 0; c < 128; c++) acc = fmaf(wr[c], xs[c], acc);

    float g = bna[o], be = bna[64 + o], mu = bna[128 + o], va = bna[192 + o];
    float s = g * rsqrtf(va + EPSV);
    float t = fmaxf((acc + ba1[o] - mu) * s + be, 0.f);
    float p = wa2[o] * t;
#pragma unroll
    for (int off = 16; off > 0; off >>= 1) p += __shfl_down_sync(0xffffffffu, p, off);
    if ((o & 31) == 0) red[o >> 5] = p;
    __syncthreads();
    if (o == 0) g_logits[bp] = red[0] + red[1] + ba2[0];
}

// ============================================================================
// Kernel 6: softmax(81) + attention-pool + final linear (128->6)
// ============================================================================
__global__ __launch_bounds__(128) void k6_final(
    const float* __restrict__ wl, const float* __restrict__ bl,
    float* __restrict__ out)
{
    __shared__ float att[81];
    __shared__ float pooled[128];
    __shared__ float red[4];
    const int b = blockIdx.x;
    const int t = threadIdx.x;

    float v = (t < 81) ? g_logits[b * 81 + t] : -1e30f;
    float mx = v;
#pragma unroll
    for (int off = 16; off > 0; off >>= 1) mx = fmaxf(mx, __shfl_xor_sync(0xffffffffu, mx, off));
    if ((t & 31) == 0) red[t >> 5] = mx;
    __syncthreads();
    mx = fmaxf(fmaxf(red[0], red[1]), fmaxf(red[2], red[3]));
    float e = (t < 81) ? expf(v - mx) : 0.f;
    __syncthreads();
    float sm = e;
#pragma unroll
    for (int off = 16; off > 0; off >>= 1) sm += __shfl_xor_sync(0xffffffffu, sm, off);
    if ((t & 31) == 0) red[t >> 5] = sm;
    __syncthreads();
    sm = red[0] + red[1] + red[2] + red[3];
    if (t < 81) att[t] = e / sm;
    __syncthreads();

    float acc = 0.f;
    const float* mr = g_merge + ((long)b * 128 + t) * 81;
#pragma unroll 9
    for (int p = 0; p < 81; p++) acc = fmaf(att[p], mr[p], acc);
    pooled[t] = acc;
    __syncthreads();

    if (t < 6) {
        float s2 = bl[t];
        const float* wr = wl + t * 128;
#pragma unroll 8
        for (int o = 0; o < 128; o++) s2 = fmaf(wr[o], pooled[o], s2);
        out[b * 6 + t] = s2;
    }
}

// ============================================================================
extern "C" void kernel_launch(void* const* d_in, const int* in_sizes, int n_in,
                              void* d_out, int out_size)
{
    const float* x    = (const float*)d_in[0];
    const float* w1   = (const float*)d_in[1];
    const float* b1   = (const float*)d_in[2];
    const float* bn1  = (const float*)d_in[3];
    const float* w2   = (const float*)d_in[4];
    const float* b2   = (const float*)d_in[5];
    const float* bn2  = (const float*)d_in[6];
    const float* wgt  = (const float*)d_in[7];
    const float* w3   = (const float*)d_in[8];
    const float* b3   = (const float*)d_in[9];
    const float* bn3  = (const float*)d_in[10];
    const float* w4   = (const float*)d_in[11];
    const float* b4   = (const float*)d_in[12];
    const float* bn4  = (const float*)d_in[13];
    const float* wa1  = (const float*)d_in[14];
    const float* ba1  = (const float*)d_in[15];
    const float* bna  = (const float*)d_in[16];
    const float* wa2  = (const float*)d_in[17];
    const float* ba2  = (const float*)d_in[18];
    const float* wl   = (const float*)d_in[19];
    const float* bl   = (const float*)d_in[20];
    float* out = (float*)d_out;

    dim3 g1(225, 4);
    k1_alignconv<<<g1, 256>>>(x, w1, b1, bn1);
    dim3 g2(162, 4);
    k2_gemm<<<g2, 256>>>(w2);
    k2e<<<2592, 256>>>(b2, bn2);
    k3_conv3<<<324, 256>>>(wgt, w3, b3, bn3);
    k4_conv4<<<324, 256>>>(w4, b4, bn4);
    k5_logits<<<256 * 81, 64>>>(wa1, ba1, bna, wa2, ba2);
    k6_final<<<256, 128>>>(wl, bl, out);
}

// round 4
// speedup vs baseline: 1.7981x; 1.3475x over previous
#include <cuda_runtime.h>
#include <cuda_bf16.h>
#include <cstdint>

#define EPSV 1e-5f

typedef unsigned long long ull;

// ---------------- scratch buffers (static, allocation-free) ----------------
__device__ __nv_bfloat16 g_y1h[256 * 225 * 128]; // bf16 hi of y1, channel-last (m, sp, c)
__device__ __nv_bfloat16 g_y1l[256 * 225 * 128]; // bf16 lo residual
__device__ __nv_bfloat16 g_w2h[128 * 6272];      // w2 hi: [n][(kh*7+kw)*128 + ci]
__device__ __nv_bfloat16 g_w2l[128 * 6272];      // w2 lo
__device__ float g_x2[256 * 128 * 81];           // x_ after conv7x7 + bn2 + relu  [b][c][81]
__device__ float g_y3[256 * 128 * 81];           // after conv3 + bn3 + relu
__device__ float g_merge[256 * 128 * 81];        // after conv4 + bn4 + relu
__device__ float g_logits[256 * 81];             // attention logits

// ---------------- PTX helpers (all baseline sm_80+ -> fine for sm_100) -----
__device__ __forceinline__ uint32_t smem_u32(const void* p) {
    uint32_t a;
    asm("{ .reg .u64 t; cvta.to.shared.u64 t, %1; cvt.u32.u64 %0, t; }" : "=r"(a) : "l"(p));
    return a;
}
__device__ __forceinline__ void cpa16(uint32_t dst, const void* src) {
    asm volatile("cp.async.ca.shared.global [%0], [%1], 16;" :: "r"(dst), "l"(src));
}
#define CP_COMMIT() asm volatile("cp.async.commit_group;" ::: "memory")
#define CP_WAIT1()  asm volatile("cp.async.wait_group 1;" ::: "memory")
#define CP_WAIT0()  asm volatile("cp.async.wait_group 0;" ::: "memory")

__device__ __forceinline__ void ldsm4(uint32_t* r, uint32_t addr) {
    asm volatile("ldmatrix.sync.aligned.m8n8.x4.shared.b16 {%0,%1,%2,%3}, [%4];"
                 : "=r"(r[0]), "=r"(r[1]), "=r"(r[2]), "=r"(r[3]) : "r"(addr));
}
__device__ __forceinline__ void mma16816(float* d, const uint32_t* a, const uint32_t* b) {
    asm volatile(
        "mma.sync.aligned.m16n8k16.row.col.f32.bf16.bf16.f32 "
        "{%0,%1,%2,%3}, {%4,%5,%6,%7}, {%8,%9}, {%0,%1,%2,%3};"
        : "+f"(d[0]), "+f"(d[1]), "+f"(d[2]), "+f"(d[3])
        : "r"(a[0]), "r"(a[1]), "r"(a[2]), "r"(a[3]), "r"(b[0]), "r"(b[1]));
}

// pack two floats to bf16x2 (lo half = f0)
__device__ __forceinline__ uint32_t cvt2(float f0, float f1) {
    uint32_t r;
    asm("cvt.rn.bf16x2.f32 %0, %1, %2;" : "=r"(r) : "f"(f1), "f"(f0));
    return r;
}

// ============================================================================
// Kernel T: reorder + bf16-split w2: [n][ci][kh][kw] -> [n][(kh*7+kw)*128+ci]
// ============================================================================
__global__ __launch_bounds__(256) void kT_w2(const float* __restrict__ w2)
{
    int t = blockIdx.x * 256 + threadIdx.x;
    if (t < 128 * 6272) {
        int n = t / 6272, k = t - n * 6272;
        int g = k >> 7, ci = k & 127;
        float v = w2[n * 6272 + ci * 49 + g];
        __nv_bfloat16 h = __float2bfloat16(v);
        g_w2h[t] = h;
        g_w2l[t] = __float2bfloat16(v - __bfloat162float(h));
    }
}

// ============================================================================
// Kernel 1: align + conv1x1 (841 -> 128) + bn1 + relu -> bf16-split, ch-last
// ============================================================================
__global__ __launch_bounds__(256) void k1_alignconv(
    const float* __restrict__ x, const float* __restrict__ w1,
    const float* __restrict__ b1, const float* __restrict__ bn1)
{
    __shared__ __align__(16) float As[32][68];
    __shared__ __align__(16) float Bs[32][132];
    const int tid = threadIdx.x;
    const int ij  = blockIdx.x;
    const int ip  = ij / 15, jp = ij - ip * 15;
    const int m0  = blockIdx.y * 64;

    const int m_l = tid & 63;
    const int klb = tid >> 6;
    const int bkl = tid & 31;
    const int bnb = tid >> 5;
    const int tm4 = (tid >> 4) << 2;
    const int tn8 = (tid & 15) << 3;

    const float* xp = x + (long)(m0 + m_l) * 50625 + ij;

    float acc[4][8];
#pragma unroll
    for (int i = 0; i < 4; i++)
#pragma unroll
        for (int j = 0; j < 8; j++) acc[i][j] = 0.f;

    for (int k0 = 0; k0 < 225; k0 += 32) {
#pragma unroll
        for (int i = 0; i < 8; i++) {
            int kl = klb + i * 4;
            int k  = k0 + kl;
            As[kl][m_l] = (k < 225) ? xp[k * 225] : 0.f;
        }
#pragma unroll
        for (int i = 0; i < 16; i++) {
            int n = bnb + i * 8;
            int k = k0 + bkl;
            float v = 0.f;
            if (k < 225) {
                int a = k / 15, bb = k - a * 15;
                v = w1[n * 841 + (a + 14 - ip) * 29 + (bb + 14 - jp)];
            }
            Bs[bkl][n] = v;
        }
        __syncthreads();
#pragma unroll
        for (int kk = 0; kk < 32; kk++) {
            float4 av  = *(const float4*)&As[kk][tm4];
            float4 bv0 = *(const float4*)&Bs[kk][tn8];
            float4 bv1 = *(const float4*)&Bs[kk][tn8 + 4];
            float a4[4] = {av.x, av.y, av.z, av.w};
            float b8[8] = {bv0.x, bv0.y, bv0.z, bv0.w, bv1.x, bv1.y, bv1.z, bv1.w};
#pragma unroll
            for (int i = 0; i < 4; i++)
#pragma unroll
                for (int j = 0; j < 8; j++) acc[i][j] = fmaf(a4[i], b8[j], acc[i][j]);
        }
        __syncthreads();
    }

    float sc[8], sh[8];
#pragma unroll
    for (int j = 0; j < 8; j++) {
        int n = tn8 + j;
        float g = bn1[n], be = bn1[128 + n], mu = bn1[256 + n], va = bn1[384 + n];
        float s = g * rsqrtf(va + EPSV);
        sc[j] = s;
        sh[j] = (b1[n] - mu) * s + be;
    }
#pragma unroll
    for (int i = 0; i < 4; i++) {
        int m = m0 + tm4 + i;
        long idx = ((long)m * 225 + ij) * 128 + tn8;
        float v[8];
#pragma unroll
        for (int j = 0; j < 8; j++) v[j] = fmaxf(fmaf(acc[i][j], sc[j], sh[j]), 0.f);
        uint32_t h01 = cvt2(v[0], v[1]);
        uint32_t h23 = cvt2(v[2], v[3]);
        uint32_t h45 = cvt2(v[4], v[5]);
        uint32_t h67 = cvt2(v[6], v[7]);
        float r0 = v[0] - __uint_as_float(h01 << 16);
        float r1 = v[1] - __uint_as_float(h01 & 0xFFFF0000u);
        float r2 = v[2] - __uint_as_float(h23 << 16);
        float r3 = v[3] - __uint_as_float(h23 & 0xFFFF0000u);
        float r4 = v[4] - __uint_as_float(h45 << 16);
        float r5 = v[5] - __uint_as_float(h45 & 0xFFFF0000u);
        float r6 = v[6] - __uint_as_float(h67 << 16);
        float r7 = v[7] - __uint_as_float(h67 & 0xFFFF0000u);
        uint32_t l01 = cvt2(r0, r1);
        uint32_t l23 = cvt2(r2, r3);
        uint32_t l45 = cvt2(r4, r5);
        uint32_t l67 = cvt2(r6, r7);
        *(uint4*)(&g_y1h[idx]) = make_uint4(h01, h23, h45, h67);
        *(uint4*)(&g_y1l[idx]) = make_uint4(l01, l23, l45, l67);
    }
}

// ============================================================================
// Kernel 2: 7x7 conv as mma.sync bf16-split implicit GEMM.
// M=20736, N=128, K=6272 in (kh,kw,ci) order. CTA tile 128x128, 8 warps
// (2Mx4N), warp tile 64x32. KT=32 double-buffered via cp.async.
// D = Ah*Bh + Ah*Bl + Al*Bh; epilogue fuses bias+bn2+relu -> g_x2 [b][c][81].
// grid 162, block 256, dynamic smem 80KB.
// ============================================================================
#define LDA    80      // padded bytes per smem row (64B data + 16B pad)
#define TILE_V 10240   // 128 rows * 80B
#define STAGE  40960   // Ah, Al, Bh, Bl
#define K2_SMEM (2 * STAGE)

__global__ __launch_bounds__(256) void k2_mma(
    const float* __restrict__ b2, const float* __restrict__ bn2)
{
    extern __shared__ char smem[];
    const uint32_t sb = smem_u32(smem);
    const int tid = threadIdx.x;
    const int w = tid >> 5, l = tid & 31;
    const int m0 = blockIdx.x * 128;
    const int warp_m = (w >> 2) * 64;
    const int warp_n = (w & 3) * 32;

    // ---- loader mapping: thread covers 32B (2x16B) per tensor-version ----
    const int lr = tid >> 1;              // row 0..127 (A: local m, B: n)
    const int lob = (tid & 1) * 32;       // byte offset within 64B row data
    const int loe = lob >> 1;             // element offset (bf16)
    {
    }
    const int gm = m0 + lr;
    const int bv = gm / 81;
    const int pos = gm - bv * 81;
    const int oh = pos / 9, ow = pos - oh * 9;
    const long a_base = ((long)bv * 225 + oh * 15 + ow) * 128;
    const __nv_bfloat16* wh_src = g_w2h + (long)lr * 6272;
    const __nv_bfloat16* wl_src = g_w2l + (long)lr * 6272;
    const uint32_t dstA = sb + lr * LDA + lob;
    const uint32_t dstB = sb + 2 * TILE_V + lr * LDA + lob;

    float acc[4][4][4];
#pragma unroll
    for (int i = 0; i < 4; i++)
#pragma unroll
        for (int j = 0; j < 4; j++)
#pragma unroll
            for (int c = 0; c < 4; c++) acc[i][j][c] = 0.f;

    // ---- stage loader ----
    auto load_stage = [&](int s, uint32_t bufoff) {
        int g  = s >> 2;
        int kh = g / 7, kw = g - kh * 7;
        long aoff = a_base + (kh * 15 + kw) * 128 + (s & 3) * 32 + loe;
        const __nv_bfloat16* pah = g_y1h + aoff;
        const __nv_bfloat16* pal = g_y1l + aoff;
        uint32_t dA = dstA + bufoff;
        cpa16(dA, pah);
        cpa16(dA + 16, pah + 8);
        cpa16(dA + TILE_V, pal);
        cpa16(dA + TILE_V + 16, pal + 8);
        long boff = (long)s * 32 + loe;
        uint32_t dB = dstB + bufoff;
        cpa16(dB, wh_src + boff);
        cpa16(dB + 16, wh_src + boff + 8);
        cpa16(dB + TILE_V, wl_src + boff);
        cpa16(dB + TILE_V + 16, wl_src + boff + 8);
    };

    // ---- compute one KT=32 stage ----
    const uint32_t aAddrM = (warp_m + (l & 15)) * LDA + ((l >> 4) << 4);
    const uint32_t bAddrN = (warp_n + (l & 7) + ((l >> 4) << 3)) * LDA + (((l >> 3) & 1) << 4);
    auto compute_stage = [&](uint32_t bufoff) {
        uint32_t base = sb + bufoff;
#pragma unroll
        for (int kstep = 0; kstep < 2; kstep++) {
            uint32_t ko = kstep * 32;
            uint32_t ah[4][4], al[4][4];
#pragma unroll
            for (int mi = 0; mi < 4; mi++) {
                uint32_t ad = base + aAddrM + mi * (16 * LDA) + ko;
                ldsm4(ah[mi], ad);
                ldsm4(al[mi], ad + TILE_V);
            }
            uint32_t bh[2][4], bl[2][4];
#pragma unroll
            for (int nb = 0; nb < 2; nb++) {
                uint32_t bd = base + 2 * TILE_V + bAddrN + nb * (16 * LDA) + ko;
                ldsm4(bh[nb], bd);
                ldsm4(bl[nb], bd + TILE_V);
            }
#pragma unroll
            for (int mi = 0; mi < 4; mi++)
#pragma unroll
                for (int nj = 0; nj < 4; nj++)
                    mma16816(acc[mi][nj], ah[mi], &bh[nj >> 1][(nj & 1) * 2]);
#pragma unroll
            for (int mi = 0; mi < 4; mi++)
#pragma unroll
                for (int nj = 0; nj < 4; nj++)
                    mma16816(acc[mi][nj], ah[mi], &bl[nj >> 1][(nj & 1) * 2]);
#pragma unroll
            for (int mi = 0; mi < 4; mi++)
#pragma unroll
                for (int nj = 0; nj < 4; nj++)
                    mma16816(acc[mi][nj], al[mi], &bh[nj >> 1][(nj & 1) * 2]);
        }
    };

    // ---- pipeline: 196 stages ----
    load_stage(0, 0);
    CP_COMMIT();
    for (int s = 0; s < 196; s++) {
        if (s + 1 < 196) load_stage(s + 1, ((s + 1) & 1) * STAGE);
        CP_COMMIT();
        CP_WAIT1();
        __syncthreads();
        compute_stage((s & 1) * STAGE);
        __syncthreads();
    }

    // ---- epilogue: bias + bn2 + relu -> g_x2 [b][c][81] ----
    float sc[4][2], sh[4][2];
#pragma unroll
    for (int nj = 0; nj < 4; nj++)
#pragma unroll
        for (int q = 0; q < 2; q++) {
            int n = warp_n + nj * 8 + (l & 3) * 2 + q;
            float g = bn2[n], be = bn2[128 + n], mu = bn2[256 + n], va = bn2[384 + n];
            float s = g * rsqrtf(va + EPSV);
            sc[nj][q] = s;
            sh[nj][q] = (b2[n] - mu) * s + be;
        }
#pragma unroll
    for (int mi = 0; mi < 4; mi++) {
#pragma unroll
        for (int half = 0; half < 2; half++) {
            int m = m0 + warp_m + mi * 16 + (l >> 2) + half * 8;
            int bb = m / 81;
            int pp = m - bb * 81;
            float* ob = g_x2 + (long)bb * 128 * 81 + pp;
#pragma unroll
            for (int nj = 0; nj < 4; nj++) {
                int n0 = warp_n + nj * 8 + (l & 3) * 2;
                float v0 = fmaxf(fmaf(acc[mi][nj][half * 2 + 0], sc[nj][0], sh[nj][0]), 0.f);
                float v1 = fmaxf(fmaf(acc[mi][nj][half * 2 + 1], sc[nj][1], sh[nj][1]), 0.f);
                ob[n0 * 81] = v0;
                ob[(n0 + 1) * 81] = v1;
            }
        }
    }
}

// ============================================================================
// Kernel 3: concat(weight(5), x_(128)) -> conv1x1 133->128 + bn3 + relu
// ============================================================================
__global__ __launch_bounds__(256) void k3_conv3(
    const float* __restrict__ wgt, const float* __restrict__ w3,
    const float* __restrict__ b3, const float* __restrict__ bn3)
{
    __shared__ __align__(16) float As[32][68];
    __shared__ __align__(16) float Bs[32][132];
    const int tid = threadIdx.x;
    const int m0  = blockIdx.x * 64;
    const int m_l = tid & 63;
    const int klb = tid >> 6;
    const int bkl = tid & 31;
    const int bnb = tid >> 5;
    const int tm4 = (tid >> 4) << 2;
    const int tn8 = (tid & 15) << 3;

    const int m   = m0 + m_l;
    const int b   = m / 81;
    const int pos = m - b * 81;

    float acc[4][8];
#pragma unroll
    for (int i = 0; i < 4; i++)
#pragma unroll
        for (int j = 0; j < 8; j++) acc[i][j] = 0.f;

    for (int k0 = 0; k0 < 160; k0 += 32) {
#pragma unroll
        for (int i = 0; i < 8; i++) {
            int kl = klb + i * 4;
            int k  = k0 + kl;
            float v = 0.f;
            if (k < 5)        v = wgt[k * 81 + pos];
            else if (k < 133) v = g_x2[((long)b * 128 + (k - 5)) * 81 + pos];
            As[kl][m_l] = v;
        }
#pragma unroll
        for (int i = 0; i < 16; i++) {
            int n = bnb + i * 8;
            int k = k0 + bkl;
            Bs[bkl][n] = (k < 133) ? w3[n * 133 + k] : 0.f;
        }
        __syncthreads();
#pragma unroll
        for (int kk = 0; kk < 32; kk++) {
            float4 av  = *(const float4*)&As[kk][tm4];
            float4 bv0 = *(const float4*)&Bs[kk][tn8];
            float4 bv1 = *(const float4*)&Bs[kk][tn8 + 4];
            float a4[4] = {av.x, av.y, av.z, av.w};
            float b8[8] = {bv0.x, bv0.y, bv0.z, bv0.w, bv1.x, bv1.y, bv1.z, bv1.w};
#pragma unroll
            for (int i = 0; i < 4; i++)
#pragma unroll
                for (int j = 0; j < 8; j++) acc[i][j] = fmaf(a4[i], b8[j], acc[i][j]);
        }
        __syncthreads();
    }

    float sc[8], sh[8];
#pragma unroll
    for (int j = 0; j < 8; j++) {
        int n = tn8 + j;
        float g = bn3[n], be = bn3[128 + n], mu = bn3[256 + n], va = bn3[384 + n];
        float s = g * rsqrtf(va + EPSV);
        sc[j] = s;
        sh[j] = (b3[n] - mu) * s + be;
    }
#pragma unroll
    for (int i = 0; i < 4; i++) {
        int mi = m0 + tm4 + i;
        int bbv = mi / 81;
        int pp = mi - bbv * 81;
#pragma unroll
        for (int j = 0; j < 8; j++) {
            int n = tn8 + j;
            g_y3[((long)bbv * 128 + n) * 81 + pp] = fmaxf(fmaf(acc[i][j], sc[j], sh[j]), 0.f);
        }
    }
}

// ============================================================================
// Kernel 4: conv1x1 128->128 + bn4 + relu -> merge
// ============================================================================
__global__ __launch_bounds__(256) void k4_conv4(
    const float* __restrict__ w4, const float* __restrict__ b4,
    const float* __restrict__ bn4)
{
    __shared__ __align__(16) float As[32][68];
    __shared__ __align__(16) float Bs[32][132];
    const int tid = threadIdx.x;
    const int m0  = blockIdx.x * 64;
    const int m_l = tid & 63;
    const int klb = tid >> 6;
    const int bkl = tid & 31;
    const int bnb = tid >> 5;
    const int tm4 = (tid >> 4) << 2;
    const int tn8 = (tid & 15) << 3;

    const int m   = m0 + m_l;
    const int b   = m / 81;
    const int pos = m - b * 81;

    float acc[4][8];
#pragma unroll
    for (int i = 0; i < 4; i++)
#pragma unroll
        for (int j = 0; j < 8; j++) acc[i][j] = 0.f;

    for (int k0 = 0; k0 < 128; k0 += 32) {
#pragma unroll
        for (int i = 0; i < 8; i++) {
            int kl = klb + i * 4;
            int k  = k0 + kl;
            As[kl][m_l] = g_y3[((long)b * 128 + k) * 81 + pos];
        }
#pragma unroll
        for (int i = 0; i < 16; i++) {
            int n = bnb + i * 8;
            Bs[bkl][n] = w4[n * 128 + k0 + bkl];
        }
        __syncthreads();
#pragma unroll
        for (int kk = 0; kk < 32; kk++) {
            float4 av  = *(const float4*)&As[kk][tm4];
            float4 bv0 = *(const float4*)&Bs[kk][tn8];
            float4 bv1 = *(const float4*)&Bs[kk][tn8 + 4];
            float a4[4] = {av.x, av.y, av.z, av.w};
            float b8[8] = {bv0.x, bv0.y, bv0.z, bv0.w, bv1.x, bv1.y, bv1.z, bv1.w};
#pragma unroll
            for (int i = 0; i < 4; i++)
#pragma unroll
                for (int j = 0; j < 8; j++) acc[i][j] = fmaf(a4[i], b8[j], acc[i][j]);
        }
        __syncthreads();
    }

    float sc[8], sh[8];
#pragma unroll
    for (int j = 0; j < 8; j++) {
        int n = tn8 + j;
        float g = bn4[n], be = bn4[128 + n], mu = bn4[256 + n], va = bn4[384 + n];
        float s = g * rsqrtf(va + EPSV);
        sc[j] = s;
        sh[j] = (b4[n] - mu) * s + be;
    }
#pragma unroll
    for (int i = 0; i < 4; i++) {
        int mi = m0 + tm4 + i;
        int bbv = mi / 81;
        int pp = mi - bbv * 81;
#pragma unroll
        for (int j = 0; j < 8; j++) {
            int n = tn8 + j;
            g_merge[((long)bbv * 128 + n) * 81 + pp] = fmaxf(fmaf(acc[i][j], sc[j], sh[j]), 0.f);
        }
    }
}

// ============================================================================
// Kernel 5: attention logits
// ============================================================================
__global__ __launch_bounds__(64) void k5_logits(
    const float* __restrict__ wa1, const float* __restrict__ ba1,
    const float* __restrict__ bna, const float* __restrict__ wa2,
    const float* __restrict__ ba2)
{
    __shared__ float xs[128];
    __shared__ float red[2];
    const int bp  = blockIdx.x;
    const int b   = bp / 81;
    const int pos = bp - b * 81;
    const int o   = threadIdx.x;  // 0..63

    xs[o]      = g_x2[((long)b * 128 + o) * 81 + pos];
    xs[o + 64] = g_x2[((long)b * 128 + o + 64) * 81 + pos];
    __syncthreads();

    float acc = 0.f;
    const float* wr = wa1 + o * 128;
#pragma unroll 8
    for (int c = 0; c < 128; c++) acc = fmaf(wr[c], xs[c], acc);

    float g = bna[o], be = bna[64 + o], mu = bna[128 + o], va = bna[192 + o];
    float s = g * rsqrtf(va + EPSV);
    float t = fmaxf((acc + ba1[o] - mu) * s + be, 0.f);
    float p = wa2[o] * t;
#pragma unroll
    for (int off = 16; off > 0; off >>= 1) p += __shfl_down_sync(0xffffffffu, p, off);
    if ((o & 31) == 0) red[o >> 5] = p;
    __syncthreads();
    if (o == 0) g_logits[bp] = red[0] + red[1] + ba2[0];
}

// ============================================================================
// Kernel 6: softmax(81) + attention-pool + final linear (128->6)
// ============================================================================
__global__ __launch_bounds__(128) void k6_final(
    const float* __restrict__ wl, const float* __restrict__ bl,
    float* __restrict__ out)
{
    __shared__ float att[81];
    __shared__ float pooled[128];
    __shared__ float red[4];
    const int b = blockIdx.x;
    const int t = threadIdx.x;

    float v = (t < 81) ? g_logits[b * 81 + t] : -1e30f;
    float mx = v;
#pragma unroll
    for (int off = 16; off > 0; off >>= 1) mx = fmaxf(mx, __shfl_xor_sync(0xffffffffu, mx, off));
    if ((t & 31) == 0) red[t >> 5] = mx;
    __syncthreads();
    mx = fmaxf(fmaxf(red[0], red[1]), fmaxf(red[2], red[3]));
    float e = (t < 81) ? expf(v - mx) : 0.f;
    __syncthreads();
    float sm = e;
#pragma unroll
    for (int off = 16; off > 0; off >>= 1) sm += __shfl_xor_sync(0xffffffffu, sm, off);
    if ((t & 31) == 0) red[t >> 5] = sm;
    __syncthreads();
    sm = red[0] + red[1] + red[2] + red[3];
    if (t < 81) att[t] = e / sm;
    __syncthreads();

    float acc = 0.f;
    const float* mr = g_merge + ((long)b * 128 + t) * 81;
#pragma unroll 9
    for (int p = 0; p < 81; p++) acc = fmaf(att[p], mr[p], acc);
    pooled[t] = acc;
    __syncthreads();

    if (t < 6) {
        float s2 = bl[t];
        const float* wr = wl + t * 128;
#pragma unroll 8
        for (int o = 0; o < 128; o++) s2 = fmaf(wr[o], pooled[o], s2);
        out[b * 6 + t] = s2;
    }
}

// ============================================================================
extern "C" void kernel_launch(void* const* d_in, const int* in_sizes, int n_in,
                              void* d_out, int out_size)
{
    const float* x    = (const float*)d_in[0];
    const float* w1   = (const float*)d_in[1];
    const float* b1   = (const float*)d_in[2];
    const float* bn1  = (const float*)d_in[3];
    const float* w2   = (const float*)d_in[4];
    const float* b2   = (const float*)d_in[5];
    const float* bn2  = (const float*)d_in[6];
    const float* wgt  = (const float*)d_in[7];
    const float* w3   = (const float*)d_in[8];
    const float* b3   = (const float*)d_in[9];
    const float* bn3  = (const float*)d_in[10];
    const float* w4   = (const float*)d_in[11];
    const float* b4   = (const float*)d_in[12];
    const float* bn4  = (const float*)d_in[13];
    const float* wa1  = (const float*)d_in[14];
    const float* ba1  = (const float*)d_in[15];
    const float* bna  = (const float*)d_in[16];
    const float* wa2  = (const float*)d_in[17];
    const float* ba2  = (const float*)d_in[18];
    const float* wl   = (const float*)d_in[19];
    const float* bl   = (const float*)d_in[20];
    float* out = (float*)d_out;

    cudaFuncSetAttribute(k2_mma, cudaFuncAttributeMaxDynamicSharedMemorySize, K2_SMEM);

    kT_w2<<<3136, 256>>>(w2);
    dim3 g1(225, 4);
    k1_alignconv<<<g1, 256>>>(x, w1, b1, bn1);
    k2_mma<<<162, 256, K2_SMEM>>>(b2, bn2);
    k3_conv3<<<324, 256>>>(wgt, w3, b3, bn3);
    k4_conv4<<<324, 256>>>(w4, b4, bn4);
    k5_logits<<<256 * 81, 64>>>(wa1, ba1, bna, wa2, ba2);
    k6_final<<<256, 128>>>(wl, bl, out);
}

// round 7
// speedup vs baseline: 1.9982x; 1.1113x over previous
#include <cuda_runtime.h>
#include <cuda_bf16.h>
#include <cstdint>

#define EPSV 1e-5f

typedef unsigned long long ull;

// ---------------- scratch buffers (static, allocation-free) ----------------
__device__ __nv_bfloat16 g_xth[225 * 256 * 256]; // x transposed+split: [ij][m][ck<=255]
__device__ __nv_bfloat16 g_xtl[225 * 256 * 256];
__device__ __nv_bfloat16 g_B1h[225 * 128 * 256]; // per-ij conv1 B matrices, split
__device__ __nv_bfloat16 g_B1l[225 * 128 * 256];
__device__ __nv_bfloat16 g_y1h[256 * 225 * 128]; // y1 split, ch-last (m, sp, c)
__device__ __nv_bfloat16 g_y1l[256 * 225 * 128];
__device__ __nv_bfloat16 g_w2h[128 * 6272];      // w2 split: [n][(kh*7+kw)*128+ci]
__device__ __nv_bfloat16 g_w2l[128 * 6272];
__device__ float         g_x2f[20736 * 128];     // x_ fp32 ch-last [m][c] (for k5)
__device__ __nv_bfloat16 g_a3h[20736 * 144];     // k3 A operand split: [m][144]
__device__ __nv_bfloat16 g_a3l[20736 * 144];     //  cols 0..4 wgt, 5..7 z, 8..135 x2, 136..143 z
__device__ __nv_bfloat16 g_w3h[128 * 144];
__device__ __nv_bfloat16 g_w3l[128 * 144];
__device__ __nv_bfloat16 g_y3h[20736 * 128];
__device__ __nv_bfloat16 g_y3l[20736 * 128];
__device__ __nv_bfloat16 g_w4h[128 * 128];
__device__ __nv_bfloat16 g_w4l[128 * 128];
__device__ float         g_merge[20736 * 128];   // fp32 ch-last [m][c]
__device__ float         g_logits[20736];

// ---------------- PTX helpers (baseline sm_80+) ----------------
__device__ __forceinline__ uint32_t smem_u32(const void* p) {
    uint32_t a;
    asm("{ .reg .u64 t; cvta.to.shared.u64 t, %1; cvt.u32.u64 %0, t; }" : "=r"(a) : "l"(p));
    return a;
}
__device__ __forceinline__ void cpa16(uint32_t dst, const void* src) {
    asm volatile("cp.async.ca.shared.global [%0], [%1], 16;" :: "r"(dst), "l"(src));
}
#define CP_COMMIT() asm volatile("cp.async.commit_group;" ::: "memory")
#define CP_WAIT1()  asm volatile("cp.async.wait_group 1;" ::: "memory")
#define CP_WAIT0()  asm volatile("cp.async.wait_group 0;" ::: "memory")

__device__ __forceinline__ void ldsm4(uint32_t* r, uint32_t addr) {
    asm volatile("ldmatrix.sync.aligned.m8n8.x4.shared.b16 {%0,%1,%2,%3}, [%4];"
                 : "=r"(r[0]), "=r"(r[1]), "=r"(r[2]), "=r"(r[3]) : "r"(addr));
}
__device__ __forceinline__ void mma16816(float* d, const uint32_t* a, const uint32_t* b) {
    asm volatile(
        "mma.sync.aligned.m16n8k16.row.col.f32.bf16.bf16.f32 "
        "{%0,%1,%2,%3}, {%4,%5,%6,%7}, {%8,%9}, {%0,%1,%2,%3};"
        : "+f"(d[0]), "+f"(d[1]), "+f"(d[2]), "+f"(d[3])
        : "r"(a[0]), "r"(a[1]), "r"(a[2]), "r"(a[3]), "r"(b[0]), "r"(b[1]));
}
// pack two floats to bf16x2 (lo half = f0)
__device__ __forceinline__ uint32_t cvt2(float f0, float f1) {
    uint32_t r;
    asm("cvt.rn.bf16x2.f32 %0, %1, %2;" : "=r"(r) : "f"(f1), "f"(f0));
    return r;
}
// split (v0,v1) into hi bf16x2 + residual bf16x2
__device__ __forceinline__ void split2(float v0, float v1, uint32_t& h, uint32_t& lo) {
    h = cvt2(v0, v1);
    float r0 = v0 - __uint_as_float(h << 16);
    float r1 = v1 - __uint_as_float(h & 0xFFFF0000u);
    lo = cvt2(r0, r1);
}

// ============================================================================
// kX: transpose + split x: x[m][c][ij] -> g_xth/l[ij][m][ck], ck 225..255 = 0
// grid (8, 256), block 256
// ============================================================================
__global__ __launch_bounds__(256) void kX(const float* __restrict__ x)
{
    __shared__ float s[225][33];
    const int tid = threadIdx.x;
    const int tx = tid & 31, ty = tid >> 5;
    const int ij0 = blockIdx.x * 32;
    const int m   = blockIdx.y;
    const int nij = (ij0 + 32 <= 225) ? 32 : (225 - ij0);

    const float* xp = x + (long)m * 50625;
    for (int cc = 0; cc < 29; cc++) {
        int c = cc * 8 + ty;
        if (c < 225) {
            float v = (tx < nij) ? xp[c * 225 + ij0 + tx] : 0.f;
            s[c][tx] = v;
        }
    }
    __syncthreads();

    for (int ii = 0; ii < nij; ii++) {
        float v = (tid < 225) ? s[tid][ii] : 0.f;
        __nv_bfloat16 h = __float2bfloat16(v);
        long idx = ((long)(ij0 + ii) * 256 + m) * 256 + tid;
        g_xth[idx] = h;
        g_xtl[idx] = __float2bfloat16(v - __bfloat162float(h));
    }
}

// ============================================================================
// kB: build per-ij conv1 B matrices from w1.  grid 225*128, block 256
// ============================================================================
__global__ __launch_bounds__(256) void kB(const float* __restrict__ w1)
{
    const int bid = blockIdx.x;
    const int ij = bid >> 7, n = bid & 127;
    const int ip = ij / 15, jp = ij - ip * 15;
    const int k = threadIdx.x;
    float v = 0.f;
    if (k < 225) {
        int a = k / 15, bb = k - a * 15;
        v = w1[n * 841 + (a + 14 - ip) * 29 + (bb + 14 - jp)];
    }
    __nv_bfloat16 h = __float2bfloat16(v);
    long idx = ((long)ij * 128 + n) * 256 + k;
    g_B1h[idx] = h;
    g_B1l[idx] = __float2bfloat16(v - __bfloat162float(h));
}

// ============================================================================
// kT2: reorder + split w2: [n][ci][kh][kw] -> [n][(kh*7+kw)*128+ci]
// ============================================================================
__global__ __launch_bounds__(256) void kT2(const float* __restrict__ w2)
{
    int t = blockIdx.x * 256 + threadIdx.x;
    if (t < 128 * 6272) {
        int n = t / 6272, k = t - n * 6272;
        int g = k >> 7, ci = k & 127;
        float v = w2[n * 6272 + ci * 49 + g];
        __nv_bfloat16 h = __float2bfloat16(v);
        g_w2h[t] = h;
        g_w2l[t] = __float2bfloat16(v - __bfloat162float(h));
    }
}

// ============================================================================
// kT3: split+pad w3 [128][133] -> [128][144] matching a3 column layout
// ============================================================================
__global__ __launch_bounds__(256) void kT3(const float* __restrict__ w3)
{
    int t = blockIdx.x * 256 + threadIdx.x;
    if (t < 128 * 144) {
        int n = t / 144, j = t - n * 144;
        float v = 0.f;
        if (j < 5)                 v = w3[n * 133 + j];
        else if (j >= 8 && j < 136) v = w3[n * 133 + j - 3];
        __nv_bfloat16 h = __float2bfloat16(v);
        g_w3h[t] = h;
        g_w3l[t] = __float2bfloat16(v - __bfloat162float(h));
    }
}

// ============================================================================
// kT4: split w4 [128][128]
// ============================================================================
__global__ __launch_bounds__(256) void kT4(const float* __restrict__ w4)
{
    int t = blockIdx.x * 256 + threadIdx.x;
    if (t < 128 * 128) {
        float v = w4[t];
        __nv_bfloat16 h = __float2bfloat16(v);
        g_w4h[t] = h;
        g_w4l[t] = __float2bfloat16(v - __bfloat162float(h));
    }
}

// ============================================================================
// kF: fill a3 cols 0..7 (wgt + zero pad) and 136..143 (zeros).  grid 1296
// ============================================================================
__global__ __launch_bounds__(256) void kF(const float* __restrict__ wgt)
{
    int t = blockIdx.x * 256 + threadIdx.x;
    if (t < 20736 * 16) {
        int m = t >> 4, jj = t & 15;
        int j = (jj < 8) ? jj : (128 + jj);
        float v = (j < 5) ? wgt[j * 81 + (m % 81)] : 0.f;
        __nv_bfloat16 h = __float2bfloat16(v);
        long idx = (long)m * 144 + j;
        g_a3h[idx] = h;
        g_a3l[idx] = __float2bfloat16(v - __bfloat162float(h));
    }
}

// ============================================================================
// k1: align-conv1 as MMA.  per ij: M=256, N=128, K=256(padded).
// grid (225, 2), block 256.  4 stages KT=64, double-buffered.
// ============================================================================
#define LDA1    144
#define T1PLANE (128 * 144)        // 18432 B per plane
#define STAGE1  (4 * T1PLANE)      // Ah, Al, Bh, Bl
#define K1_SMEM (2 * STAGE1)       // 147456

__global__ __launch_bounds__(256) void k1_mma(
    const float* __restrict__ b1, const float* __restrict__ bn1)
{
    extern __shared__ char smem[];
    const uint32_t sb = smem_u32(smem);
    const int tid = threadIdx.x;
    const int w = tid >> 5, l = tid & 31;
    const int ij = blockIdx.x;
    const int m0 = blockIdx.y * 128;
    const int warp_m = (w >> 2) * 64;
    const int warp_n = (w & 3) * 32;

    const int row = tid & 127, ver = tid >> 7;
    const __nv_bfloat16* asrc = (ver ? g_xtl : g_xth) + ((long)ij * 256 + m0 + row) * 256;
    const __nv_bfloat16* bsrc = (ver ? g_B1l : g_B1h) + ((long)ij * 128 + row) * 256;
    const uint32_t dA = sb + ver * T1PLANE + row * LDA1;
    const uint32_t dB = sb + 2 * T1PLANE + ver * T1PLANE + row * LDA1;

    float acc[4][4][4];
#pragma unroll
    for (int i = 0; i < 4; i++)
#pragma unroll
        for (int j = 0; j < 4; j++)
#pragma unroll
            for (int c = 0; c < 4; c++) acc[i][j][c] = 0.f;

    // full stage = KT=64 bf16 = 128B per row -> 8 x cp.async.16 per operand
    auto load_stage = [&](int s, uint32_t off) {
#pragma unroll
        for (int j = 0; j < 8; j++) {
            cpa16(dA + off + j * 16, asrc + s * 64 + j * 8);
            cpa16(dB + off + j * 16, bsrc + s * 64 + j * 8);
        }
    };

    const uint32_t aAddrM = (warp_m + (l & 15)) * LDA1 + ((l >> 4) << 4);
    const uint32_t bAddrN = (warp_n + (l & 7) + ((l >> 4) << 3)) * LDA1 + (((l >> 3) & 1) << 4);
    auto compute_stage = [&](uint32_t off) {
        uint32_t base = sb + off;
#pragma unroll
        for (int ks = 0; ks < 4; ks++) {
            uint32_t ko = ks * 32;
            uint32_t ah[4][4], al[4][4];
#pragma unroll
            for (int mi = 0; mi < 4; mi++) {
                uint32_t ad = base + aAddrM + mi * (16 * LDA1) + ko;
                ldsm4(ah[mi], ad);
                ldsm4(al[mi], ad + T1PLANE);
            }
            uint32_t bh[2][4], bl[2][4];
#pragma unroll
            for (int nb = 0; nb < 2; nb++) {
                uint32_t bd = base + 2 * T1PLANE + bAddrN + nb * (16 * LDA1) + ko;
                ldsm4(bh[nb], bd);
                ldsm4(bl[nb], bd + T1PLANE);
            }
#pragma unroll
            for (int mi = 0; mi < 4; mi++)
#pragma unroll
                for (int nj = 0; nj < 4; nj++)
                    mma16816(acc[mi][nj], ah[mi], &bh[nj >> 1][(nj & 1) * 2]);
#pragma unroll
            for (int mi = 0; mi < 4; mi++)
#pragma unroll
                for (int nj = 0; nj < 4; nj++)
                    mma16816(acc[mi][nj], ah[mi], &bl[nj >> 1][(nj & 1) * 2]);
#pragma unroll
            for (int mi = 0; mi < 4; mi++)
#pragma unroll
                for (int nj = 0; nj < 4; nj++)
                    mma16816(acc[mi][nj], al[mi], &bh[nj >> 1][(nj & 1) * 2]);
        }
    };

    load_stage(0, 0);
    CP_COMMIT();
    for (int s = 0; s < 4; s++) {
        if (s + 1 < 4) load_stage(s + 1, ((s + 1) & 1) * STAGE1);
        CP_COMMIT();
        CP_WAIT1();
        __syncthreads();
        compute_stage((s & 1) * STAGE1);
        __syncthreads();
    }

    // epilogue: bn1 + relu -> split -> g_y1h/l [m][225][128]
    float sc[4][2], sh[4][2];
#pragma unroll
    for (int nj = 0; nj < 4; nj++)
#pragma unroll
        for (int q = 0; q < 2; q++) {
            int n = warp_n + nj * 8 + (l & 3) * 2 + q;
            float g = bn1[n], be = bn1[128 + n], mu = bn1[256 + n], va = bn1[384 + n];
            float s = g * rsqrtf(va + EPSV);
            sc[nj][q] = s;
            sh[nj][q] = (b1[n] - mu) * s + be;
        }
#pragma unroll
    for (int mi = 0; mi < 4; mi++)
#pragma unroll
        for (int half = 0; half < 2; half++) {
            int m = m0 + warp_m + mi * 16 + (l >> 2) + half * 8;
            long base = ((long)m * 225 + ij) * 128;
#pragma unroll
            for (int nj = 0; nj < 4; nj++) {
                int n0 = warp_n + nj * 8 + (l & 3) * 2;
                float v0 = fmaxf(fmaf(acc[mi][nj][half * 2 + 0], sc[nj][0], sh[nj][0]), 0.f);
                float v1 = fmaxf(fmaf(acc[mi][nj][half * 2 + 1], sc[nj][1], sh[nj][1]), 0.f);
                uint32_t h, lo;
                split2(v0, v1, h, lo);
                *(uint32_t*)&g_y1h[base + n0] = h;
                *(uint32_t*)&g_y1l[base + n0] = lo;
            }
        }
}

// ============================================================================
// k2: 7x7 conv MMA, M=20736 N=128 K=6272.  (proven in R4; new epilogue)
// grid 162, block 256, 80KB smem.
// ============================================================================
#define LDA    80
#define TILE_V 10240
#define STAGE  40960
#define K2_SMEM (2 * STAGE)

__global__ __launch_bounds__(256) void k2_mma(
    const float* __restrict__ b2, const float* __restrict__ bn2)
{
    extern __shared__ char smem[];
    const uint32_t sb = smem_u32(smem);
    const int tid = threadIdx.x;
    const int w = tid >> 5, l = tid & 31;
    const int m0 = blockIdx.x * 128;
    const int warp_m = (w >> 2) * 64;
    const int warp_n = (w & 3) * 32;

    const int lr = tid >> 1;
    const int lob = (tid & 1) * 32;
    const int loe = lob >> 1;
    const int gm = m0 + lr;
    const int bv = gm / 81;
    const int pos = gm - bv * 81;
    const int oh = pos / 9, ow = pos - oh * 9;
    const long a_base = ((long)bv * 225 + oh * 15 + ow) * 128;
    const __nv_bfloat16* wh_src = g_w2h + (long)lr * 6272;
    const __nv_bfloat16* wl_src = g_w2l + (long)lr * 6272;
    const uint32_t dstA = sb + lr * LDA + lob;
    const uint32_t dstB = sb + 2 * TILE_V + lr * LDA + lob;

    float acc[4][4][4];
#pragma unroll
    for (int i = 0; i < 4; i++)
#pragma unroll
        for (int j = 0; j < 4; j++)
#pragma unroll
            for (int c = 0; c < 4; c++) acc[i][j][c] = 0.f;

    auto load_stage = [&](int s, uint32_t bufoff) {
        int g  = s >> 2;
        int kh = g / 7, kw = g - kh * 7;
        long aoff = a_base + (kh * 15 + kw) * 128 + (s & 3) * 32 + loe;
        const __nv_bfloat16* pah = g_y1h + aoff;
        const __nv_bfloat16* pal = g_y1l + aoff;
        uint32_t dA = dstA + bufoff;
        cpa16(dA, pah);
        cpa16(dA + 16, pah + 8);
        cpa16(dA + TILE_V, pal);
        cpa16(dA + TILE_V + 16, pal + 8);
        long boff = (long)s * 32 + loe;
        uint32_t dB = dstB + bufoff;
        cpa16(dB, wh_src + boff);
        cpa16(dB + 16, wh_src + boff + 8);
        cpa16(dB + TILE_V, wl_src + boff);
        cpa16(dB + TILE_V + 16, wl_src + boff + 8);
    };

    const uint32_t aAddrM = (warp_m + (l & 15)) * LDA + ((l >> 4) << 4);
    const uint32_t bAddrN = (warp_n + (l & 7) + ((l >> 4) << 3)) * LDA + (((l >> 3) & 1) << 4);
    auto compute_stage = [&](uint32_t bufoff) {
        uint32_t base = sb + bufoff;
#pragma unroll
        for (int kstep = 0; kstep < 2; kstep++) {
            uint32_t ko = kstep * 32;
            uint32_t ah[4][4], al[4][4];
#pragma unroll
            for (int mi = 0; mi < 4; mi++) {
                uint32_t ad = base + aAddrM + mi * (16 * LDA) + ko;
                ldsm4(ah[mi], ad);
                ldsm4(al[mi], ad + TILE_V);
            }
            uint32_t bh[2][4], bl[2][4];
#pragma unroll
            for (int nb = 0; nb < 2; nb++) {
                uint32_t bd = base + 2 * TILE_V + bAddrN + nb * (16 * LDA) + ko;
                ldsm4(bh[nb], bd);
                ldsm4(bl[nb], bd + TILE_V);
            }
#pragma unroll
            for (int mi = 0; mi < 4; mi++)
#pragma unroll
                for (int nj = 0; nj < 4; nj++)
                    mma16816(acc[mi][nj], ah[mi], &bh[nj >> 1][(nj & 1) * 2]);
#pragma unroll
            for (int mi = 0; mi < 4; mi++)
#pragma unroll
                for (int nj = 0; nj < 4; nj++)
                    mma16816(acc[mi][nj], ah[mi], &bl[nj >> 1][(nj & 1) * 2]);
#pragma unroll
            for (int mi = 0; mi < 4; mi++)
#pragma unroll
                for (int nj = 0; nj < 4; nj++)
                    mma16816(acc[mi][nj], al[mi], &bh[nj >> 1][(nj & 1) * 2]);
        }
    };

    load_stage(0, 0);
    CP_COMMIT();
    for (int s = 0; s < 196; s++) {
        if (s + 1 < 196) load_stage(s + 1, ((s + 1) & 1) * STAGE);
        CP_COMMIT();
        CP_WAIT1();
        __syncthreads();
        compute_stage((s & 1) * STAGE);
        __syncthreads();
    }

    // epilogue: bias + bn2 + relu -> g_x2f fp32 ch-last AND g_a3h/l split (+8 col offset)
    float sc[4][2], sh[4][2];
#pragma unroll
    for (int nj = 0; nj < 4; nj++)
#pragma unroll
        for (int q = 0; q < 2; q++) {
            int n = warp_n + nj * 8 + (l & 3) * 2 + q;
            float g = bn2[n], be = bn2[128 + n], mu = bn2[256 + n], va = bn2[384 + n];
            float s = g * rsqrtf(va + EPSV);
            sc[nj][q] = s;
            sh[nj][q] = (b2[n] - mu) * s + be;
        }
#pragma unroll
    for (int mi = 0; mi < 4; mi++)
#pragma unroll
        for (int half = 0; half < 2; half++) {
            int m = m0 + warp_m + mi * 16 + (l >> 2) + half * 8;
#pragma unroll
            for (int nj = 0; nj < 4; nj++) {
                int n0 = warp_n + nj * 8 + (l & 3) * 2;
                float v0 = fmaxf(fmaf(acc[mi][nj][half * 2 + 0], sc[nj][0], sh[nj][0]), 0.f);
                float v1 = fmaxf(fmaf(acc[mi][nj][half * 2 + 1], sc[nj][1], sh[nj][1]), 0.f);
                *(float2*)&g_x2f[(long)m * 128 + n0] = make_float2(v0, v1);
                uint32_t h, lo;
                split2(v0, v1, h, lo);
                *(uint32_t*)&g_a3h[(long)m * 144 + 8 + n0] = h;
                *(uint32_t*)&g_a3l[(long)m * 144 + 8 + n0] = lo;
            }
        }
}

// ============================================================================
// k3: conv1x1 144->128 MMA (monolithic smem), grid 162, block 256
// ============================================================================
#define LDA3    304
#define T3PLANE (128 * 304)
#define K3_SMEM (4 * T3PLANE)   // 155648

__global__ __launch_bounds__(256) void k3_mma(
    const float* __restrict__ b3, const float* __restrict__ bn3)
{
    extern __shared__ char smem[];
    const uint32_t sb = smem_u32(smem);
    const int tid = threadIdx.x;
    const int w = tid >> 5, l = tid & 31;
    const int m0 = blockIdx.x * 128;
    const int warp_m = (w >> 2) * 64;
    const int warp_n = (w & 3) * 32;

    const int row = tid & 127, ver = tid >> 7;
    const __nv_bfloat16* asrc = (ver ? g_a3l : g_a3h) + (long)(m0 + row) * 144;
    const __nv_bfloat16* bsrc = (ver ? g_w3l : g_w3h) + row * 144;
    const uint32_t dA = sb + ver * T3PLANE + row * LDA3;
    const uint32_t dB = sb + 2 * T3PLANE + ver * T3PLANE + row * LDA3;
#pragma unroll
    for (int j = 0; j < 18; j++) {
        cpa16(dA + j * 16, asrc + j * 8);
        cpa16(dB + j * 16, bsrc + j * 8);
    }
    CP_COMMIT();

    float acc[4][4][4];
#pragma unroll
    for (int i = 0; i < 4; i++)
#pragma unroll
        for (int j = 0; j < 4; j++)
#pragma unroll
            for (int c = 0; c < 4; c++) acc[i][j][c] = 0.f;

    CP_WAIT0();
    __syncthreads();

    const uint32_t aAddrM = (warp_m + (l & 15)) * LDA3 + ((l >> 4) << 4);
    const uint32_t bAddrN = (warp_n + (l & 7) + ((l >> 4) << 3)) * LDA3 + (((l >> 3) & 1) << 4);
#pragma unroll
    for (int ks = 0; ks < 9; ks++) {
        uint32_t ko = ks * 32;
        uint32_t ah[4][4], al[4][4];
#pragma unroll
        for (int mi = 0; mi < 4; mi++) {
            uint32_t ad = sb + aAddrM + mi * (16 * LDA3) + ko;
            ldsm4(ah[mi], ad);
            ldsm4(al[mi], ad + T3PLANE);
        }
        uint32_t bh[2][4], bl[2][4];
#pragma unroll
        for (int nb = 0; nb < 2; nb++) {
            uint32_t bd = sb + 2 * T3PLANE + bAddrN + nb * (16 * LDA3) + ko;
            ldsm4(bh[nb], bd);
            ldsm4(bl[nb], bd + T3PLANE);
        }
#pragma unroll
        for (int mi = 0; mi < 4; mi++)
#pragma unroll
            for (int nj = 0; nj < 4; nj++)
                mma16816(acc[mi][nj], ah[mi], &bh[nj >> 1][(nj & 1) * 2]);
#pragma unroll
        for (int mi = 0; mi < 4; mi++)
#pragma unroll
            for (int nj = 0; nj < 4; nj++)
                mma16816(acc[mi][nj], ah[mi], &bl[nj >> 1][(nj & 1) * 2]);
#pragma unroll
        for (int mi = 0; mi < 4; mi++)
#pragma unroll
            for (int nj = 0; nj < 4; nj++)
                mma16816(acc[mi][nj], al[mi], &bh[nj >> 1][(nj & 1) * 2]);
    }

    float sc[4][2], sh[4][2];
#pragma unroll
    for (int nj = 0; nj < 4; nj++)
#pragma unroll
        for (int q = 0; q < 2; q++) {
            int n = warp_n + nj * 8 + (l & 3) * 2 + q;
            float g = bn3[n], be = bn3[128 + n], mu = bn3[256 + n], va = bn3[384 + n];
            float s = g * rsqrtf(va + EPSV);
            sc[nj][q] = s;
            sh[nj][q] = (b3[n] - mu) * s + be;
        }
#pragma unroll
    for (int mi = 0; mi < 4; mi++)
#pragma unroll
        for (int half = 0; half < 2; half++) {
            int m = m0 + warp_m + mi * 16 + (l >> 2) + half * 8;
#pragma unroll
            for (int nj = 0; nj < 4; nj++) {
                int n0 = warp_n + nj * 8 + (l & 3) * 2;
                float v0 = fmaxf(fmaf(acc[mi][nj][half * 2 + 0], sc[nj][0], sh[nj][0]), 0.f);
                float v1 = fmaxf(fmaf(acc[mi][nj][half * 2 + 1], sc[nj][1], sh[nj][1]), 0.f);
                uint32_t h, lo;
                split2(v0, v1, h, lo);
                *(uint32_t*)&g_y3h[(long)m * 128 + n0] = h;
                *(uint32_t*)&g_y3l[(long)m * 128 + n0] = lo;
            }
        }
}

// ============================================================================
// k4: conv1x1 128->128 MMA (monolithic smem) -> g_merge fp32 ch-last
// ============================================================================
#define LDA4    272
#define T4PLANE (128 * 272)
#define K4_SMEM (4 * T4PLANE)   // 139264

__global__ __launch_bounds__(256) void k4_mma(
    const float* __restrict__ b4, const float* __restrict__ bn4)
{
    extern __shared__ char smem[];
    const uint32_t sb = smem_u32(smem);
    const int tid = threadIdx.x;
    const int w = tid >> 5, l = tid & 31;
    const int m0 = blockIdx.x * 128;
    const int warp_m = (w >> 2) * 64;
    const int warp_n = (w & 3) * 32;

    const int row = tid & 127, ver = tid >> 7;
    const __nv_bfloat16* asrc = (ver ? g_y3l : g_y3h) + (long)(m0 + row) * 128;
    const __nv_bfloat16* bsrc = (ver ? g_w4l : g_w4h) + row * 128;
    const uint32_t dA = sb + ver * T4PLANE + row * LDA4;
    const uint32_t dB = sb + 2 * T4PLANE + ver * T4PLANE + row * LDA4;
#pragma unroll
    for (int j = 0; j < 16; j++) {
        cpa16(dA + j * 16, asrc + j * 8);
        cpa16(dB + j * 16, bsrc + j * 8);
    }
    CP_COMMIT();

    float acc[4][4][4];
#pragma unroll
    for (int i = 0; i < 4; i++)
#pragma unroll
        for (int j = 0; j < 4; j++)
#pragma unroll
            for (int c = 0; c < 4; c++) acc[i][j][c] = 0.f;

    CP_WAIT0();
    __syncthreads();

    const uint32_t aAddrM = (warp_m + (l & 15)) * LDA4 + ((l >> 4) << 4);
    const uint32_t bAddrN = (warp_n + (l & 7) + ((l >> 4) << 3)) * LDA4 + (((l >> 3) & 1) << 4);
#pragma unroll
    for (int ks = 0; ks < 8; ks++) {
        uint32_t ko = ks * 32;
        uint32_t ah[4][4], al[4][4];
#pragma unroll
        for (int mi = 0; mi < 4; mi++) {
            uint32_t ad = sb + aAddrM + mi * (16 * LDA4) + ko;
            ldsm4(ah[mi], ad);
            ldsm4(al[mi], ad + T4PLANE);
        }
        uint32_t bh[2][4], bl[2][4];
#pragma unroll
        for (int nb = 0; nb < 2; nb++) {
            uint32_t bd = sb + 2 * T4PLANE + bAddrN + nb * (16 * LDA4) + ko;
            ldsm4(bh[nb], bd);
            ldsm4(bl[nb], bd + T4PLANE);
        }
#pragma unroll
        for (int mi = 0; mi < 4; mi++)
#pragma unroll
            for (int nj = 0; nj < 4; nj++)
                mma16816(acc[mi][nj], ah[mi], &bh[nj >> 1][(nj & 1) * 2]);
#pragma unroll
        for (int mi = 0; mi < 4; mi++)
#pragma unroll
            for (int nj = 0; nj < 4; nj++)
                mma16816(acc[mi][nj], ah[mi], &bl[nj >> 1][(nj & 1) * 2]);
#pragma unroll
        for (int mi = 0; mi < 4; mi++)
#pragma unroll
            for (int nj = 0; nj < 4; nj++)
                mma16816(acc[mi][nj], al[mi], &bh[nj >> 1][(nj & 1) * 2]);
    }

    float sc[4][2], sh[4][2];
#pragma unroll
    for (int nj = 0; nj < 4; nj++)
#pragma unroll
        for (int q = 0; q < 2; q++) {
            int n = warp_n + nj * 8 + (l & 3) * 2 + q;
            float g = bn4[n], be = bn4[128 + n], mu = bn4[256 + n], va = bn4[384 + n];
            float s = g * rsqrtf(va + EPSV);
            sc[nj][q] = s;
            sh[nj][q] = (b4[n] - mu) * s + be;
        }
#pragma unroll
    for (int mi = 0; mi < 4; mi++)
#pragma unroll
        for (int half = 0; half < 2; half++) {
            int m = m0 + warp_m + mi * 16 + (l >> 2) + half * 8;
#pragma unroll
            for (int nj = 0; nj < 4; nj++) {
                int n0 = warp_n + nj * 8 + (l & 3) * 2;
                float v0 = fmaxf(fmaf(acc[mi][nj][half * 2 + 0], sc[nj][0], sh[nj][0]), 0.f);
                float v1 = fmaxf(fmaf(acc[mi][nj][half * 2 + 1], sc[nj][1], sh[nj][1]), 0.f);
                *(float2*)&g_merge[(long)m * 128 + n0] = make_float2(v0, v1);
            }
        }
}

// ============================================================================
// k5: attention logits (coalesced ch-last reads).  grid 20736, block 64
// ============================================================================
__global__ __launch_bounds__(64) void k5_logits(
    const float* __restrict__ wa1, const float* __restrict__ ba1,
    const float* __restrict__ bna, const float* __restrict__ wa2,
    const float* __restrict__ ba2)
{
    __shared__ float xs[128];
    __shared__ float red[2];
    const int m = blockIdx.x;
    const int o = threadIdx.x;

    xs[o]      = g_x2f[(long)m * 128 + o];
    xs[o + 64] = g_x2f[(long)m * 128 + o + 64];
    __syncthreads();

    float acc = 0.f;
    const float* wr = wa1 + o * 128;
#pragma unroll 8
    for (int c = 0; c < 128; c++) acc = fmaf(wr[c], xs[c], acc);

    float g = bna[o], be = bna[64 + o], mu = bna[128 + o], va = bna[192 + o];
    float s = g * rsqrtf(va + EPSV);
    float t = fmaxf((acc + ba1[o] - mu) * s + be, 0.f);
    float p = wa2[o] * t;
#pragma unroll
    for (int off = 16; off > 0; off >>= 1) p += __shfl_down_sync(0xffffffffu, p, off);
    if ((o & 31) == 0) red[o >> 5] = p;
    __syncthreads();
    if (o == 0) g_logits[m] = red[0] + red[1] + ba2[0];
}

// ============================================================================
// k6: softmax(81) + attention-pool + final linear (128->6).  grid 256, block 128
// ============================================================================
__global__ __launch_bounds__(128) void k6_final(
    const float* __restrict__ wl, const float* __restrict__ bl,
    float* __restrict__ out)
{
    __shared__ float att[81];
    __shared__ float pooled[128];
    __shared__ float red[4];
    const int b = blockIdx.x;
    const int t = threadIdx.x;

    float v = (t < 81) ? g_logits[b * 81 + t] : -1e30f;
    float mx = v;
#pragma unroll
    for (int off = 16; off > 0; off >>= 1) mx = fmaxf(mx, __shfl_xor_sync(0xffffffffu, mx, off));
    if ((t & 31) == 0) red[t >> 5] = mx;
    __syncthreads();
    mx = fmaxf(fmaxf(red[0], red[1]), fmaxf(red[2], red[3]));
    float e = (t < 81) ? expf(v - mx) : 0.f;
    __syncthreads();
    float sm = e;
#pragma unroll
    for (int off = 16; off > 0; off >>= 1) sm += __shfl_xor_sync(0xffffffffu, sm, off);
    if ((t & 31) == 0) red[t >> 5] = sm;
    __syncthreads();
    sm = red[0] + red[1] + red[2] + red[3];
    if (t < 81) att[t] = e / sm;
    __syncthreads();

    float acc = 0.f;
    const float* mr = g_merge + (long)b * 81 * 128 + t;
#pragma unroll 9
    for (int p = 0; p < 81; p++) acc = fmaf(att[p], mr[p * 128], acc);
    pooled[t] = acc;
    __syncthreads();

    if (t < 6) {
        float s2 = bl[t];
        const float* wr = wl + t * 128;
#pragma unroll 8
        for (int o = 0; o < 128; o++) s2 = fmaf(wr[o], pooled[o], s2);
        out[b * 6 + t] = s2;
    }
}

// ============================================================================
extern "C" void kernel_launch(void* const* d_in, const int* in_sizes, int n_in,
                              void* d_out, int out_size)
{
    const float* x    = (const float*)d_in[0];
    const float* w1   = (const float*)d_in[1];
    const float* b1   = (const float*)d_in[2];
    const float* bn1  = (const float*)d_in[3];
    const float* w2   = (const float*)d_in[4];
    const float* b2   = (const float*)d_in[5];
    const float* bn2  = (const float*)d_in[6];
    const float* wgt  = (const float*)d_in[7];
    const float* w3   = (const float*)d_in[8];
    const float* b3   = (const float*)d_in[9];
    const float* bn3  = (const float*)d_in[10];
    const float* w4   = (const float*)d_in[11];
    const float* b4   = (const float*)d_in[12];
    const float* bn4  = (const float*)d_in[13];
    const float* wa1  = (const float*)d_in[14];
    const float* ba1  = (const float*)d_in[15];
    const float* bna  = (const float*)d_in[16];
    const float* wa2  = (const float*)d_in[17];
    const float* ba2  = (const float*)d_in[18];
    const float* wl   = (const float*)d_in[19];
    const float* bl   = (const float*)d_in[20];
    float* out = (float*)d_out;

    cudaFuncSetAttribute(k1_mma, cudaFuncAttributeMaxDynamicSharedMemorySize, K1_SMEM);
    cudaFuncSetAttribute(k2_mma, cudaFuncAttributeMaxDynamicSharedMemorySize, K2_SMEM);
    cudaFuncSetAttribute(k3_mma, cudaFuncAttributeMaxDynamicSharedMemorySize, K3_SMEM);
    cudaFuncSetAttribute(k4_mma, cudaFuncAttributeMaxDynamicSharedMemorySize, K4_SMEM);

    dim3 gX(8, 256);
    kX<<<gX, 256>>>(x);
    kB<<<225 * 128, 256>>>(w1);
    kT2<<<3136, 256>>>(w2);
    kT3<<<72, 256>>>(w3);
    kT4<<<64, 256>>>(w4);
    kF<<<1296, 256>>>(wgt);

    dim3 g1(225, 2);
    k1_mma<<<g1, 256, K1_SMEM>>>(b1, bn1);
    k2_mma<<<162, 256, K2_SMEM>>>(b2, bn2);
    k3_mma<<<162, 256, K3_SMEM>>>(b3, bn3);
    k4_mma<<<162, 256, K4_SMEM>>>(b4, bn4);
    k5_logits<<<20736, 64>>>(wa1, ba1, bna, wa2, ba2);
    k6_final<<<256, 128>>>(wl, bl, out);
}